// round 12
// baseline (speedup 1.0000x reference)
#include <cuda_runtime.h>
#include <cuda_bf16.h>
#include <cstdint>

#define NN 100000
#define NE 640000
#define INC 256
#define HID 128
#define NB  ((NN + 1023) / 1024)

// ---------------- scratch (__device__ globals) ----------------
__device__ float g_h[(size_t)NN * HID];    // GEMM1 output
__device__ float g_h2[(size_t)NN * HID];   // fused prop1+GEMM2 output
__device__ __nv_bfloat16 g_w1hi[INC * HID];      // [n=128][k=256]
__device__ __nv_bfloat16 g_w1lo[INC * HID];
__device__ __nv_bfloat16 g_w2hi[HID * HID];      // [n=128][k=128]
__device__ __nv_bfloat16 g_w2lo[HID * HID];
__device__ float g_dinv[NN];
__device__ int   g_cnt[NN];          // zero on entry; re-zeroed by k_alloc
__device__ int   g_off[NN];
__device__ int   g_end[NN];
__device__ int   g_cursor[NN];
__device__ int   g_es[NE];
__device__ float g_en[NE];
__device__ int   g_total;

__device__ __forceinline__ void split_bf16(float x, unsigned short& hi, unsigned short& lo) {
    __nv_bfloat16 h = __float2bfloat16(x);
    float hf = __bfloat162float(h);
    __nv_bfloat16 l = __float2bfloat16(x - hf);
    hi = *reinterpret_cast<unsigned short*>(&h);
    lo = *reinterpret_cast<unsigned short*>(&l);
}

// in-register truncation split of a float2 -> packed bf16x2 hi & lo words
__device__ __forceinline__ void cvt_pair(float2 v, uint32_t& hi, uint32_t& lo) {
    uint32_t x0 = __float_as_uint(v.x), x1 = __float_as_uint(v.y);
    hi = __byte_perm(x0, x1, 0x7632);
    float l0 = v.x - __uint_as_float(x0 & 0xffff0000u);
    float l1 = v.y - __uint_as_float(x1 & 0xffff0000u);
    asm("cvt.rn.bf16x2.f32 %0, %1, %2;" : "=r"(lo) : "f"(l1), "f"(l0));
}

__device__ __forceinline__ uint32_t smem_u32(const void* p) {
    uint32_t a;
    asm("{ .reg .u64 t; cvta.to.shared.u64 t, %1; cvt.u32.u64 %0, t; }" : "=r"(a) : "l"(p));
    return a;
}

#define CP16(d, s) asm volatile("cp.async.cg.shared.global [%0], [%1], 16;" :: "r"(d), "l"(s) : "memory")
#define CPC()      asm volatile("cp.async.commit_group;" ::: "memory")
#define CPW(n)     asm volatile("cp.async.wait_group %0;" :: "n"(n) : "memory")

#define MMA_BF16(c0,c1,c2,c3,a0,a1,a2,a3,b0,b1)                                  \
    asm volatile("mma.sync.aligned.m16n8k16.row.col.f32.bf16.bf16.f32 "          \
        "{%0,%1,%2,%3}, {%4,%5,%6,%7}, {%8,%9}, {%0,%1,%2,%3};"                  \
        : "+f"(c0), "+f"(c1), "+f"(c2), "+f"(c3)                                  \
        : "r"(a0), "r"(a1), "r"(a2), "r"(a3), "r"(b0), "r"(b1))

// ---------------------------------------------------------------------------
// W1 conversion (must precede GEMM1, main stream)
// ---------------------------------------------------------------------------
__global__ void k_convw1(const float* __restrict__ W1) {
    int i = blockIdx.x * 256 + threadIdx.x;      // i = n*256 + k, 32768 total
    int n = i >> 8, k = i & 255;
    unsigned short h, l;
    split_bf16(W1[k * 128 + n], h, l);
    g_w1hi[i] = *(__nv_bfloat16*)&h;
    g_w1lo[i] = *(__nv_bfloat16*)&l;
}

// ---------------------------------------------------------------------------
// Side-stream: degree count (blocks 0..2499) + convW2 (2500..2563) + reset
// ---------------------------------------------------------------------------
__global__ void k_count_init(const int* __restrict__ dst,
                             const float* __restrict__ Wmu,
                             const float* __restrict__ Wlv)
{
    int b = blockIdx.x;
    int t = threadIdx.x;
    if (b == 0 && t == 0) g_total = 0;
    if (b < 2500) {
        int e = b * 256 + t;                 // NE = 2500*256 exactly
        atomicAdd(&g_cnt[dst[e]], 1);
    } else {
        int i = (b - 2500) * 256 + t;        // i = n*128 + k, 16384 total
        int n = i >> 7, k = i & 127;
        float v = (n < 64) ? Wmu[k * 64 + n] : Wlv[k * 64 + (n - 64)];
        unsigned short h, l;
        split_bf16(v, h, l);
        g_w2hi[i] = *(__nv_bfloat16*)&h;
        g_w2lo[i] = *(__nv_bfloat16*)&l;
    }
}

// ---------------------------------------------------------------------------
// Segment allocation: block-local scan + atomic base grab (+dinv, cnt reset)
// ---------------------------------------------------------------------------
__global__ __launch_bounds__(1024) void k_alloc() {
    __shared__ int sm[1024];
    __shared__ int base;
    const int t = threadIdx.x;
    const int i = blockIdx.x * 1024 + t;
    int v = 0;
    if (i < NN) {
        v = g_cnt[i];
        g_cnt[i] = 0;
        g_dinv[i] = rsqrtf(1.0f + (float)v);
    }
    sm[t] = v;
    __syncthreads();
#pragma unroll
    for (int d = 1; d < 1024; d <<= 1) {
        int x = (t >= d) ? sm[t - d] : 0;
        __syncthreads();
        sm[t] += x;
        __syncthreads();
    }
    if (t == 1023) base = atomicAdd(&g_total, sm[1023]);
    __syncthreads();
    if (i < NN) {
        int off = base + sm[t] - v;
        g_off[i] = off;
        g_end[i] = off + v;
        g_cursor[i] = off;
    }
}

__global__ void k_scatter(const int* __restrict__ src, const int* __restrict__ dst) {
    int e = blockIdx.x * blockDim.x + threadIdx.x;
    if (e >= NE) return;
    int s = src[e], d = dst[e];
    int pos = atomicAdd(&g_cursor[d], 1);
    g_es[pos] = s;
    g_en[pos] = g_dinv[s] * g_dinv[d];
}

// ---------------------------------------------------------------------------
// GEMM1: C[M,128] = x @ W^T, A = raw fp32 (in-register truncation split),
// B = preconverted bf16 hi/lo planes. cp.async double buffer.
// ---------------------------------------------------------------------------
#define LDAF  36
#define APLANE (128 * LDAF * 4)
#define LDB   40
#define BPLANE (128 * LDB * 2)
#define FBUF  (APLANE + 2 * BPLANE)
#define SMEM_F (2 * FBUF)

__global__ __launch_bounds__(256, 2) void tgemm_f32a(
    const float* __restrict__ A,
    const __nv_bfloat16* __restrict__ Bhi, const __nv_bfloat16* __restrict__ Blo,
    float* __restrict__ C, int M)
{
    extern __shared__ char sm[];
    const uint32_t smb = smem_u32(sm);
    constexpr int KT = INC;

    const int t = threadIdx.x;
    const int w = t >> 5;
    const int lane = t & 31;
    const int g = lane >> 2;
    const int tg = lane & 3;
    const int warp_m = (w & 3) * 32;
    const int warp_n = (w >> 2) * 64;
    const int blockRow = blockIdx.x * 128;

    const int lr = t >> 1;
    const int koA = (t & 1) * 16;
    const int koB = (t & 1) * 16;
    int grow = blockRow + lr;
    if (grow > M - 1) grow = M - 1;
    const float* ap = A + (size_t)grow * KT + koA;
    const __nv_bfloat16* bpH = Bhi + (size_t)lr * KT + koB;
    const __nv_bfloat16* bpL = Blo + (size_t)lr * KT + koB;
    const uint32_t dstA = smb + lr * (LDAF * 4) + koA * 4;
    const uint32_t dstB = smb + APLANE + lr * (LDB * 2) + koB * 2;

    float acc[2][8][4];
#pragma unroll
    for (int i = 0; i < 2; i++)
#pragma unroll
        for (int j = 0; j < 8; j++)
#pragma unroll
            for (int k = 0; k < 4; k++) acc[i][j][k] = 0.0f;

    constexpr int NCHUNK = KT / 32;

    CP16(dstA,      ap);      CP16(dstA + 16, ap + 4);
    CP16(dstA + 32, ap + 8);  CP16(dstA + 48, ap + 12);
    CP16(dstB,              bpH);  CP16(dstB + 16,          bpH + 8);
    CP16(dstB + BPLANE,     bpL);  CP16(dstB + BPLANE + 16, bpL + 8);
    CPC();

    int cur = 0;
#pragma unroll 1
    for (int c = 0; c < NCHUNK; c++) {
        if (c + 1 < NCHUNK) {
            const int kt = (c + 1) * 32;
            const uint32_t dA = dstA + (cur ^ 1) * FBUF;
            const uint32_t dB = dstB + (cur ^ 1) * FBUF;
            CP16(dA,      ap + kt);      CP16(dA + 16, ap + kt + 4);
            CP16(dA + 32, ap + kt + 8);  CP16(dA + 48, ap + kt + 12);
            CP16(dB,              bpH + kt);  CP16(dB + 16,          bpH + kt + 8);
            CP16(dB + BPLANE,     bpL + kt);  CP16(dB + BPLANE + 16, bpL + kt + 8);
            CPC();
            CPW(1);
        } else {
            CPW(0);
        }
        __syncthreads();

        const float* sA = (const float*)(sm + (size_t)cur * FBUF);
        const unsigned short* sBhi = (const unsigned short*)(sm + (size_t)cur * FBUF + APLANE);
        const unsigned short* sBlo = (const unsigned short*)(sm + (size_t)cur * FBUF + APLANE + BPLANE);

#pragma unroll
        for (int ks = 0; ks < 2; ks++) {
            const int c0 = ks * 16 + 2 * tg;
            uint32_t ah[2][4], al[2][4];
#pragma unroll
            for (int mf = 0; mf < 2; mf++) {
                const int r0 = warp_m + mf * 16 + g;
                float2 v0 = *(const float2*)&sA[(size_t)r0 * LDAF + c0];
                float2 v1 = *(const float2*)&sA[(size_t)(r0 + 8) * LDAF + c0];
                float2 v2 = *(const float2*)&sA[(size_t)r0 * LDAF + c0 + 8];
                float2 v3 = *(const float2*)&sA[(size_t)(r0 + 8) * LDAF + c0 + 8];
                cvt_pair(v0, ah[mf][0], al[mf][0]);
                cvt_pair(v1, ah[mf][1], al[mf][1]);
                cvt_pair(v2, ah[mf][2], al[mf][2]);
                cvt_pair(v3, ah[mf][3], al[mf][3]);
            }
            uint32_t bh[8][2], bl[8][2];
#pragma unroll
            for (int nf = 0; nf < 8; nf++) {
                const int n = warp_n + nf * 8 + g;
                bh[nf][0] = *(const uint32_t*)&sBhi[(size_t)n * LDB + c0];
                bh[nf][1] = *(const uint32_t*)&sBhi[(size_t)n * LDB + c0 + 8];
                bl[nf][0] = *(const uint32_t*)&sBlo[(size_t)n * LDB + c0];
                bl[nf][1] = *(const uint32_t*)&sBlo[(size_t)n * LDB + c0 + 8];
            }
#pragma unroll
            for (int nf = 0; nf < 8; nf++) {
                MMA_BF16(acc[0][nf][0], acc[0][nf][1], acc[0][nf][2], acc[0][nf][3],
                         ah[0][0], ah[0][1], ah[0][2], ah[0][3], bh[nf][0], bh[nf][1]);
                MMA_BF16(acc[1][nf][0], acc[1][nf][1], acc[1][nf][2], acc[1][nf][3],
                         ah[1][0], ah[1][1], ah[1][2], ah[1][3], bh[nf][0], bh[nf][1]);
            }
#pragma unroll
            for (int nf = 0; nf < 8; nf++) {
                MMA_BF16(acc[0][nf][0], acc[0][nf][1], acc[0][nf][2], acc[0][nf][3],
                         ah[0][0], ah[0][1], ah[0][2], ah[0][3], bl[nf][0], bl[nf][1]);
                MMA_BF16(acc[1][nf][0], acc[1][nf][1], acc[1][nf][2], acc[1][nf][3],
                         ah[1][0], ah[1][1], ah[1][2], ah[1][3], bl[nf][0], bl[nf][1]);
            }
#pragma unroll
            for (int nf = 0; nf < 8; nf++) {
                MMA_BF16(acc[0][nf][0], acc[0][nf][1], acc[0][nf][2], acc[0][nf][3],
                         al[0][0], al[0][1], al[0][2], al[0][3], bh[nf][0], bh[nf][1]);
                MMA_BF16(acc[1][nf][0], acc[1][nf][1], acc[1][nf][2], acc[1][nf][3],
                         al[1][0], al[1][1], al[1][2], al[1][3], bh[nf][0], bh[nf][1]);
            }
        }
        __syncthreads();
        cur ^= 1;
    }

#pragma unroll
    for (int mf = 0; mf < 2; mf++) {
#pragma unroll
        for (int nf = 0; nf < 8; nf++) {
            const int row0 = blockRow + warp_m + mf * 16 + g;
            const int col = warp_n + nf * 8 + 2 * tg;
            if (row0 < M)
                *(float2*)(C + (size_t)row0 * 128 + col) =
                    make_float2(acc[mf][nf][0], acc[mf][nf][1]);
            if (row0 + 8 < M)
                *(float2*)(C + (size_t)(row0 + 8) * 128 + col) =
                    make_float2(acc[mf][nf][2], acc[mf][nf][3]);
        }
    }
}

// ---------------------------------------------------------------------------
// FUSED prop1 + GEMM2:
//  phase 1: each CTA propagates its 128 rows (gather from g_h via CSR),
//           ReLU + rn-split -> smem A bf16 planes (LDA2=136 shorts/row).
//  phase 2: GEMM2 mainloop, A from smem, B (weights) cp.async double buffer.
//  Output -> g_h2 (separate buffer; g_h is still being gathered by other CTAs).
// ---------------------------------------------------------------------------
#define LDA2   136                       // shorts per A row (128 data + 8 pad)
#define A2BYTES (128 * LDA2 * 2)         // 34816 per plane
#define OFF_A2LO A2BYTES
#define OFF_B2   (2 * A2BYTES)           // 69632
#define B2PLANE  (128 * LDB * 2)         // 10240
#define B2BUF    (2 * B2PLANE)           // 20480 (hi+lo)
#define SMEM_PG  (OFF_B2 + 2 * B2BUF)    // 110592

__global__ __launch_bounds__(256, 2) void k_prop_gemm2(
    const float* __restrict__ H,
    const float* __restrict__ b1,
    const __nv_bfloat16* __restrict__ Bhi, const __nv_bfloat16* __restrict__ Blo,
    float* __restrict__ C, int M)
{
    extern __shared__ char sm[];
    const uint32_t smb = smem_u32(sm);
    constexpr int KT = HID;

    const int t = threadIdx.x;
    const int w = t >> 5;
    const int lane = t & 31;
    const int g = lane >> 2;
    const int tg = lane & 3;
    const int warp_m = (w & 3) * 32;
    const int warp_n = (w >> 2) * 64;
    const int blockRow = blockIdx.x * 128;

    // --- B staging mapping (same as old tgemm_bf16) ---
    const int lr = t >> 1;
    const int ko = (t & 1) * 16;
    const __nv_bfloat16* bpH = Bhi + (size_t)lr * KT + ko;
    const __nv_bfloat16* bpL = Blo + (size_t)lr * KT + ko;
    const uint32_t dstB = smb + OFF_B2 + lr * (LDB * 2) + ko * 2;

    // prologue: issue B chunk 0 into buffer 0 (overlaps phase-1 gather)
    CP16(dstB,           bpH);  CP16(dstB + 16,           bpH + 8);
    CP16(dstB + B2PLANE, bpL);  CP16(dstB + B2PLANE + 16, bpL + 8);
    CPC();

    // ---------------- phase 1: propagate 16 rows per warp into smem A ------
    {
        float4 bb = ((const float4*)b1)[lane];
#pragma unroll 1
        for (int i = 0; i < 16; i++) {
            const int nodeLocal = w * 16 + i;
            const int warp = blockRow + nodeLocal;   // node id
            uint32_t hiw0 = 0, hiw1 = 0, low0 = 0, low1 = 0;
            if (warp < NN) {
                float di = g_dinv[warp];
                float s = di * di;
                float4 v = ((const float4*)(H + (size_t)warp * HID))[lane];
                float ax = fmaf(v.x, s, bb.x);
                float ay = fmaf(v.y, s, bb.y);
                float az = fmaf(v.z, s, bb.z);
                float aw = fmaf(v.w, s, bb.w);

                int e = g_off[warp];
                const int end = g_end[warp];
                for (; e + 4 <= end; e += 4) {
                    int s0 = g_es[e], s1 = g_es[e + 1], s2 = g_es[e + 2], s3 = g_es[e + 3];
                    float m0 = g_en[e], m1 = g_en[e + 1], m2 = g_en[e + 2], m3 = g_en[e + 3];
                    float4 v0 = ((const float4*)(H + (size_t)s0 * HID))[lane];
                    float4 v1 = ((const float4*)(H + (size_t)s1 * HID))[lane];
                    float4 v2 = ((const float4*)(H + (size_t)s2 * HID))[lane];
                    float4 v3 = ((const float4*)(H + (size_t)s3 * HID))[lane];
                    ax = fmaf(v0.x, m0, ax); ay = fmaf(v0.y, m0, ay);
                    az = fmaf(v0.z, m0, az); aw = fmaf(v0.w, m0, aw);
                    ax = fmaf(v1.x, m1, ax); ay = fmaf(v1.y, m1, ay);
                    az = fmaf(v1.z, m1, az); aw = fmaf(v1.w, m1, aw);
                    ax = fmaf(v2.x, m2, ax); ay = fmaf(v2.y, m2, ay);
                    az = fmaf(v2.z, m2, az); aw = fmaf(v2.w, m2, aw);
                    ax = fmaf(v3.x, m3, ax); ay = fmaf(v3.y, m3, ay);
                    az = fmaf(v3.z, m3, az); aw = fmaf(v3.w, m3, aw);
                }
                for (; e < end; e++) {
                    int s0 = g_es[e];
                    float m0 = g_en[e];
                    float4 v0 = ((const float4*)(H + (size_t)s0 * HID))[lane];
                    ax = fmaf(v0.x, m0, ax); ay = fmaf(v0.y, m0, ay);
                    az = fmaf(v0.z, m0, az); aw = fmaf(v0.w, m0, aw);
                }

                ax = fmaxf(ax, 0.f); ay = fmaxf(ay, 0.f);
                az = fmaxf(az, 0.f); aw = fmaxf(aw, 0.f);
                unsigned short h[4], l[4];
                split_bf16(ax, h[0], l[0]); split_bf16(ay, h[1], l[1]);
                split_bf16(az, h[2], l[2]); split_bf16(aw, h[3], l[3]);
                hiw0 = h[0] | ((uint32_t)h[1] << 16);
                hiw1 = h[2] | ((uint32_t)h[3] << 16);
                low0 = l[0] | ((uint32_t)l[1] << 16);
                low1 = l[2] | ((uint32_t)l[3] << 16);
            }
            const uint32_t off = (uint32_t)nodeLocal * (LDA2 * 2) + lane * 8;
            *(uint2*)(sm + off)            = make_uint2(hiw0, hiw1);
            *(uint2*)(sm + OFF_A2LO + off) = make_uint2(low0, low1);
        }
    }

    // ---------------- phase 2: GEMM with A in smem, B double-buffered ------
    float acc[2][8][4];
#pragma unroll
    for (int i = 0; i < 2; i++)
#pragma unroll
        for (int j = 0; j < 8; j++)
#pragma unroll
            for (int k = 0; k < 4; k++) acc[i][j][k] = 0.0f;

    const unsigned short* sAhi = (const unsigned short*)(sm);
    const unsigned short* sAlo = (const unsigned short*)(sm + OFF_A2LO);

    constexpr int NCHUNK = KT / 32;    // 4
    int cur = 0;
#pragma unroll 1
    for (int c = 0; c < NCHUNK; c++) {
        if (c + 1 < NCHUNK) {
            const int kt = (c + 1) * 32;
            const uint32_t dB = dstB + (cur ^ 1) * B2BUF;
            CP16(dB,           bpH + kt);  CP16(dB + 16,           bpH + kt + 8);
            CP16(dB + B2PLANE, bpL + kt);  CP16(dB + B2PLANE + 16, bpL + kt + 8);
            CPC();
            CPW(1);
        } else {
            CPW(0);
        }
        __syncthreads();   // first iteration: also orders phase-1 A stores

        const unsigned short* sBhi = (const unsigned short*)(sm + OFF_B2 + (size_t)cur * B2BUF);
        const unsigned short* sBlo = (const unsigned short*)(sm + OFF_B2 + (size_t)cur * B2BUF + B2PLANE);

#pragma unroll
        for (int ks = 0; ks < 2; ks++) {
            const int cA = c * 32 + ks * 16 + 2 * tg;   // A col within full K
            const int cB = ks * 16 + 2 * tg;            // B col within chunk
            uint32_t ah[2][4], al[2][4];
#pragma unroll
            for (int mf = 0; mf < 2; mf++) {
                const int r0 = warp_m + mf * 16 + g;
                ah[mf][0] = *(const uint32_t*)&sAhi[(size_t)r0 * LDA2 + cA];
                ah[mf][1] = *(const uint32_t*)&sAhi[(size_t)(r0 + 8) * LDA2 + cA];
                ah[mf][2] = *(const uint32_t*)&sAhi[(size_t)r0 * LDA2 + cA + 8];
                ah[mf][3] = *(const uint32_t*)&sAhi[(size_t)(r0 + 8) * LDA2 + cA + 8];
                al[mf][0] = *(const uint32_t*)&sAlo[(size_t)r0 * LDA2 + cA];
                al[mf][1] = *(const uint32_t*)&sAlo[(size_t)(r0 + 8) * LDA2 + cA];
                al[mf][2] = *(const uint32_t*)&sAlo[(size_t)r0 * LDA2 + cA + 8];
                al[mf][3] = *(const uint32_t*)&sAlo[(size_t)(r0 + 8) * LDA2 + cA + 8];
            }
            uint32_t bh[8][2], bl[8][2];
#pragma unroll
            for (int nf = 0; nf < 8; nf++) {
                const int n = warp_n + nf * 8 + g;
                bh[nf][0] = *(const uint32_t*)&sBhi[(size_t)n * LDB + cB];
                bh[nf][1] = *(const uint32_t*)&sBhi[(size_t)n * LDB + cB + 8];
                bl[nf][0] = *(const uint32_t*)&sBlo[(size_t)n * LDB + cB];
                bl[nf][1] = *(const uint32_t*)&sBlo[(size_t)n * LDB + cB + 8];
            }
#pragma unroll
            for (int nf = 0; nf < 8; nf++) {
                MMA_BF16(acc[0][nf][0], acc[0][nf][1], acc[0][nf][2], acc[0][nf][3],
                         ah[0][0], ah[0][1], ah[0][2], ah[0][3], bh[nf][0], bh[nf][1]);
                MMA_BF16(acc[1][nf][0], acc[1][nf][1], acc[1][nf][2], acc[1][nf][3],
                         ah[1][0], ah[1][1], ah[1][2], ah[1][3], bh[nf][0], bh[nf][1]);
            }
#pragma unroll
            for (int nf = 0; nf < 8; nf++) {
                MMA_BF16(acc[0][nf][0], acc[0][nf][1], acc[0][nf][2], acc[0][nf][3],
                         ah[0][0], ah[0][1], ah[0][2], ah[0][3], bl[nf][0], bl[nf][1]);
                MMA_BF16(acc[1][nf][0], acc[1][nf][1], acc[1][nf][2], acc[1][nf][3],
                         ah[1][0], ah[1][1], ah[1][2], ah[1][3], bl[nf][0], bl[nf][1]);
            }
#pragma unroll
            for (int nf = 0; nf < 8; nf++) {
                MMA_BF16(acc[0][nf][0], acc[0][nf][1], acc[0][nf][2], acc[0][nf][3],
                         al[0][0], al[0][1], al[0][2], al[0][3], bh[nf][0], bh[nf][1]);
                MMA_BF16(acc[1][nf][0], acc[1][nf][1], acc[1][nf][2], acc[1][nf][3],
                         al[1][0], al[1][1], al[1][2], al[1][3], bh[nf][0], bh[nf][1]);
            }
        }
        __syncthreads();
        cur ^= 1;
    }

    // epilogue -> g_h2
#pragma unroll
    for (int mf = 0; mf < 2; mf++) {
#pragma unroll
        for (int nf = 0; nf < 8; nf++) {
            const int row0 = blockRow + warp_m + mf * 16 + g;
            const int col = warp_n + nf * 8 + 2 * tg;
            if (row0 < M)
                *(float2*)(C + (size_t)row0 * 128 + col) =
                    make_float2(acc[mf][nf][0], acc[mf][nf][1]);
            if (row0 + 8 < M)
                *(float2*)(C + (size_t)(row0 + 8) * 128 + col) =
                    make_float2(acc[mf][nf][2], acc[mf][nf][3]);
        }
    }
}

// ---------------------------------------------------------------------------
// prop2: final propagation to split output (mu | logvar), reads g_h2
// ---------------------------------------------------------------------------
__global__ __launch_bounds__(256) void k_prop_csr_out(
    const float* __restrict__ H,
    const float* __restrict__ bmu,
    const float* __restrict__ blv,
    float* __restrict__ out)
{
    int warp = (blockIdx.x * blockDim.x + threadIdx.x) >> 5;
    if (warp >= NN) return;
    int lane = threadIdx.x & 31;

    float di = g_dinv[warp];
    float s = di * di;
    float4 bb;
    float* dstp;
    if (lane < 16) {
        bb = ((const float4*)bmu)[lane];
        dstp = out + (size_t)warp * 64 + lane * 4;
    } else {
        bb = ((const float4*)blv)[lane - 16];
        dstp = out + (size_t)NN * 64 + (size_t)warp * 64 + (lane - 16) * 4;
    }
    float4 v = ((const float4*)(H + (size_t)warp * HID))[lane];
    float ax = fmaf(v.x, s, bb.x);
    float ay = fmaf(v.y, s, bb.y);
    float az = fmaf(v.z, s, bb.z);
    float aw = fmaf(v.w, s, bb.w);

    int e = g_off[warp];
    const int end = g_end[warp];
    for (; e + 4 <= end; e += 4) {
        int s0 = g_es[e], s1 = g_es[e + 1], s2 = g_es[e + 2], s3 = g_es[e + 3];
        float m0 = g_en[e], m1 = g_en[e + 1], m2 = g_en[e + 2], m3 = g_en[e + 3];
        float4 v0 = ((const float4*)(H + (size_t)s0 * HID))[lane];
        float4 v1 = ((const float4*)(H + (size_t)s1 * HID))[lane];
        float4 v2 = ((const float4*)(H + (size_t)s2 * HID))[lane];
        float4 v3 = ((const float4*)(H + (size_t)s3 * HID))[lane];
        ax = fmaf(v0.x, m0, ax); ay = fmaf(v0.y, m0, ay);
        az = fmaf(v0.z, m0, az); aw = fmaf(v0.w, m0, aw);
        ax = fmaf(v1.x, m1, ax); ay = fmaf(v1.y, m1, ay);
        az = fmaf(v1.z, m1, az); aw = fmaf(v1.w, m1, aw);
        ax = fmaf(v2.x, m2, ax); ay = fmaf(v2.y, m2, ay);
        az = fmaf(v2.z, m2, az); aw = fmaf(v2.w, m2, aw);
        ax = fmaf(v3.x, m3, ax); ay = fmaf(v3.y, m3, ay);
        az = fmaf(v3.z, m3, az); aw = fmaf(v3.w, m3, aw);
    }
    for (; e < end; e++) {
        int s0 = g_es[e];
        float m0 = g_en[e];
        float4 v0 = ((const float4*)(H + (size_t)s0 * HID))[lane];
        ax = fmaf(v0.x, m0, ax); ay = fmaf(v0.y, m0, ay);
        az = fmaf(v0.z, m0, az); aw = fmaf(v0.w, m0, aw);
    }

    *(float4*)dstp = make_float4(ax, ay, az, aw);
}

// ---------------------------------------------------------------------------
extern "C" void kernel_launch(void* const* d_in, const int* in_sizes, int n_in,
                              void* d_out, int out_size)
{
    const float* x   = (const float*)d_in[0];
    const int*   ei  = (const int*)d_in[1];
    const float* W1  = (const float*)d_in[2];
    const float* b1  = (const float*)d_in[3];
    const float* Wmu = (const float*)d_in[4];
    const float* bmu = (const float*)d_in[5];
    const float* Wlv = (const float*)d_in[6];
    const float* blv = (const float*)d_in[7];
    float* out = (float*)d_out;

    const int* src = ei;
    const int* dst = ei + NE;

    float *h_ptr, *h2_ptr;
    cudaGetSymbolAddress((void**)&h_ptr, g_h);
    cudaGetSymbolAddress((void**)&h2_ptr, g_h2);
    __nv_bfloat16 *w1hi, *w1lo, *w2hi, *w2lo;
    cudaGetSymbolAddress((void**)&w1hi, g_w1hi);
    cudaGetSymbolAddress((void**)&w1lo, g_w1lo);
    cudaGetSymbolAddress((void**)&w2hi, g_w2hi);
    cudaGetSymbolAddress((void**)&w2lo, g_w2lo);

    cudaFuncSetAttribute(tgemm_f32a, cudaFuncAttributeMaxDynamicSharedMemorySize, SMEM_F);
    cudaFuncSetAttribute(k_prop_gemm2, cudaFuncAttributeMaxDynamicSharedMemorySize, SMEM_PG);

    const int TB = 256;

    // Side stream + fork/join events (host-side only; created per call)
    cudaStream_t s2;
    cudaStreamCreateWithFlags(&s2, cudaStreamNonBlocking);
    cudaEvent_t ev_fork, ev_join;
    cudaEventCreateWithFlags(&ev_fork, cudaEventDisableTiming);
    cudaEventCreateWithFlags(&ev_join, cudaEventDisableTiming);

    // --- main stream: W1 conversion (GEMM1 dependency) ---
    k_convw1<<<128, TB>>>(W1);

    // --- fork: CSR build on s2, concurrent with GEMM1 on main ---
    cudaEventRecord(ev_fork, 0);
    cudaStreamWaitEvent(s2, ev_fork, 0);

    k_count_init<<<2564, TB, 0, s2>>>(dst, Wmu, Wlv);
    k_alloc<<<NB, 1024, 0, s2>>>();
    k_scatter<<<(NE + TB - 1) / TB, TB, 0, s2>>>(src, dst);
    cudaEventRecord(ev_join, s2);

    // --- main stream: Layer 1 GEMM ---
    tgemm_f32a<<<(NN + 127) / 128, 256, SMEM_F>>>(x, w1hi, w1lo, h_ptr, NN);

    // --- join: fused kernel needs both GEMM1 and CSR ---
    cudaStreamWaitEvent(0, ev_join, 0);

    // --- FUSED prop1 + GEMM2: g_h -> g_h2 ---
    k_prop_gemm2<<<(NN + 127) / 128, 256, SMEM_PG>>>(h_ptr, b1, w2hi, w2lo, h2_ptr, NN);

    // --- prop2 to split output ---
    k_prop_csr_out<<<(NN * 32 + TB - 1) / TB, TB>>>(h2_ptr, bmu, blv, out);
}

// round 13
// speedup vs baseline: 1.1218x; 1.1218x over previous
#include <cuda_runtime.h>
#include <cuda_bf16.h>
#include <cstdint>

#define NN 100000
#define NE 640000
#define INC 256
#define HID 128
#define NB  ((NN + 1023) / 1024)

// ---------------- scratch (__device__ globals) ----------------
__device__ float g_h[(size_t)NN * HID];
__device__ __nv_bfloat16 g_hhi[(size_t)NN * HID];
__device__ __nv_bfloat16 g_hlo[(size_t)NN * HID];
__device__ __nv_bfloat16 g_w1hi[INC * HID];      // [n=128][k=256]
__device__ __nv_bfloat16 g_w1lo[INC * HID];
__device__ __nv_bfloat16 g_w2hi[HID * HID];      // [n=128][k=128]
__device__ __nv_bfloat16 g_w2lo[HID * HID];
__device__ float g_dinv[NN];
__device__ int   g_cnt[NN];          // zero on entry; re-zeroed by k_alloc
__device__ int   g_off[NN];
__device__ int   g_end[NN];
__device__ int   g_cursor[NN];
__device__ int   g_es[NE];
__device__ float g_en[NE];
__device__ int   g_total;

__device__ __forceinline__ void split_bf16(float x, unsigned short& hi, unsigned short& lo) {
    __nv_bfloat16 h = __float2bfloat16(x);
    float hf = __bfloat162float(h);
    __nv_bfloat16 l = __float2bfloat16(x - hf);
    hi = *reinterpret_cast<unsigned short*>(&h);
    lo = *reinterpret_cast<unsigned short*>(&l);
}

__device__ __forceinline__ void cvt_pair(float2 v, uint32_t& hi, uint32_t& lo) {
    uint32_t x0 = __float_as_uint(v.x), x1 = __float_as_uint(v.y);
    hi = __byte_perm(x0, x1, 0x7632);
    float l0 = v.x - __uint_as_float(x0 & 0xffff0000u);
    float l1 = v.y - __uint_as_float(x1 & 0xffff0000u);
    asm("cvt.rn.bf16x2.f32 %0, %1, %2;" : "=r"(lo) : "f"(l1), "f"(l0));
}

__device__ __forceinline__ uint32_t smem_u32(const void* p) {
    uint32_t a;
    asm("{ .reg .u64 t; cvta.to.shared.u64 t, %1; cvt.u32.u64 %0, t; }" : "=r"(a) : "l"(p));
    return a;
}

__device__ __forceinline__ void ldsm4(uint32_t& d0, uint32_t& d1, uint32_t& d2, uint32_t& d3,
                                      uint32_t addr) {
    asm volatile("ldmatrix.sync.aligned.m8n8.x4.shared.b16 {%0,%1,%2,%3}, [%4];"
                 : "=r"(d0), "=r"(d1), "=r"(d2), "=r"(d3) : "r"(addr));
}

#define CP16(d, s) asm volatile("cp.async.cg.shared.global [%0], [%1], 16;" :: "r"(d), "l"(s) : "memory")
#define CPC()      asm volatile("cp.async.commit_group;" ::: "memory")
#define CPW(n)     asm volatile("cp.async.wait_group %0;" :: "n"(n) : "memory")

#define MMA_BF16(c0,c1,c2,c3,a0,a1,a2,a3,b0,b1)                                  \
    asm volatile("mma.sync.aligned.m16n8k16.row.col.f32.bf16.bf16.f32 "          \
        "{%0,%1,%2,%3}, {%4,%5,%6,%7}, {%8,%9}, {%0,%1,%2,%3};"                  \
        : "+f"(c0), "+f"(c1), "+f"(c2), "+f"(c3)                                  \
        : "r"(a0), "r"(a1), "r"(a2), "r"(a3), "r"(b0), "r"(b1))

// ---------------------------------------------------------------------------
// W1 conversion (must precede GEMM1, main stream)
// ---------------------------------------------------------------------------
__global__ void k_convw1(const float* __restrict__ W1) {
    int i = blockIdx.x * 256 + threadIdx.x;      // i = n*256 + k, 32768 total
    int n = i >> 8, k = i & 255;
    unsigned short h, l;
    split_bf16(W1[k * 128 + n], h, l);
    g_w1hi[i] = *(__nv_bfloat16*)&h;
    g_w1lo[i] = *(__nv_bfloat16*)&l;
}

// ---------------------------------------------------------------------------
// Side-stream: degree count (blocks 0..2499) + convW2 (2500..2563) + reset
// ---------------------------------------------------------------------------
__global__ void k_count_init(const int* __restrict__ dst,
                             const float* __restrict__ Wmu,
                             const float* __restrict__ Wlv)
{
    int b = blockIdx.x;
    int t = threadIdx.x;
    if (b == 0 && t == 0) g_total = 0;
    if (b < 2500) {
        int e = b * 256 + t;                 // NE = 2500*256 exactly
        atomicAdd(&g_cnt[dst[e]], 1);
    } else {
        int i = (b - 2500) * 256 + t;        // i = n*128 + k, 16384 total
        int n = i >> 7, k = i & 127;
        float v = (n < 64) ? Wmu[k * 64 + n] : Wlv[k * 64 + (n - 64)];
        unsigned short h, l;
        split_bf16(v, h, l);
        g_w2hi[i] = *(__nv_bfloat16*)&h;
        g_w2lo[i] = *(__nv_bfloat16*)&l;
    }
}

// ---------------------------------------------------------------------------
// Segment allocation: block-local scan + atomic base grab (+dinv, cnt reset)
// ---------------------------------------------------------------------------
__global__ __launch_bounds__(1024) void k_alloc() {
    __shared__ int sm[1024];
    __shared__ int base;
    const int t = threadIdx.x;
    const int i = blockIdx.x * 1024 + t;
    int v = 0;
    if (i < NN) {
        v = g_cnt[i];
        g_cnt[i] = 0;
        g_dinv[i] = rsqrtf(1.0f + (float)v);
    }
    sm[t] = v;
    __syncthreads();
#pragma unroll
    for (int d = 1; d < 1024; d <<= 1) {
        int x = (t >= d) ? sm[t - d] : 0;
        __syncthreads();
        sm[t] += x;
        __syncthreads();
    }
    if (t == 1023) base = atomicAdd(&g_total, sm[1023]);
    __syncthreads();
    if (i < NN) {
        int off = base + sm[t] - v;
        g_off[i] = off;
        g_end[i] = off + v;
        g_cursor[i] = off;
    }
}

__global__ void k_scatter(const int* __restrict__ src, const int* __restrict__ dst) {
    int e = blockIdx.x * blockDim.x + threadIdx.x;
    if (e >= NE) return;
    int s = src[e], d = dst[e];
    int pos = atomicAdd(&g_cursor[d], 1);
    g_es[pos] = s;
    g_en[pos] = g_dinv[s] * g_dinv[d];
}

// ---------------------------------------------------------------------------
// GEMM1: C[M,128] = x @ W^T, A = raw fp32 (in-register truncation split),
// B = preconverted bf16 hi/lo planes (LDSM fragment loads). cp.async dbuf.
// ---------------------------------------------------------------------------
#define LDAF  36
#define APLANE (128 * LDAF * 4)
#define LDB   40
#define BPLANE (128 * LDB * 2)
#define FBUF  (APLANE + 2 * BPLANE)
#define SMEM_F (2 * FBUF)

__global__ __launch_bounds__(256, 2) void tgemm_f32a(
    const float* __restrict__ A,
    const __nv_bfloat16* __restrict__ Bhi, const __nv_bfloat16* __restrict__ Blo,
    float* __restrict__ C, int M)
{
    extern __shared__ char sm[];
    const uint32_t smb = smem_u32(sm);
    constexpr int KT = INC;

    const int t = threadIdx.x;
    const int w = t >> 5;
    const int lane = t & 31;
    const int g = lane >> 2;
    const int tg = lane & 3;
    const int warp_m = (w & 3) * 32;
    const int warp_n = (w >> 2) * 64;
    const int blockRow = blockIdx.x * 128;

    // LDSM lane roles
    const int q = lane >> 3;
    const int s8 = lane & 7;
    // B lane offsets (bytes within a plane) for nf-pair p (covers nf=2p,2p+1)
    uint32_t bLane[4];
#pragma unroll
    for (int p = 0; p < 4; p++)
        bLane[p] = (uint32_t)(warp_n + p * 16 + ((q >> 1) << 3) + s8) * (LDB * 2) + (q & 1) * 16;

    const int lr = t >> 1;
    const int koA = (t & 1) * 16;
    const int koB = (t & 1) * 16;
    int grow = blockRow + lr;
    if (grow > M - 1) grow = M - 1;
    const float* ap = A + (size_t)grow * KT + koA;
    const __nv_bfloat16* bpH = Bhi + (size_t)lr * KT + koB;
    const __nv_bfloat16* bpL = Blo + (size_t)lr * KT + koB;
    const uint32_t dstA = smb + lr * (LDAF * 4) + koA * 4;
    const uint32_t dstB = smb + APLANE + lr * (LDB * 2) + koB * 2;

    float acc[2][8][4];
#pragma unroll
    for (int i = 0; i < 2; i++)
#pragma unroll
        for (int j = 0; j < 8; j++)
#pragma unroll
            for (int k = 0; k < 4; k++) acc[i][j][k] = 0.0f;

    constexpr int NCHUNK = KT / 32;

    CP16(dstA,      ap);      CP16(dstA + 16, ap + 4);
    CP16(dstA + 32, ap + 8);  CP16(dstA + 48, ap + 12);
    CP16(dstB,              bpH);  CP16(dstB + 16,          bpH + 8);
    CP16(dstB + BPLANE,     bpL);  CP16(dstB + BPLANE + 16, bpL + 8);
    CPC();

    int cur = 0;
#pragma unroll 1
    for (int c = 0; c < NCHUNK; c++) {
        if (c + 1 < NCHUNK) {
            const int kt = (c + 1) * 32;
            const uint32_t dA = dstA + (cur ^ 1) * FBUF;
            const uint32_t dB = dstB + (cur ^ 1) * FBUF;
            CP16(dA,      ap + kt);      CP16(dA + 16, ap + kt + 4);
            CP16(dA + 32, ap + kt + 8);  CP16(dA + 48, ap + kt + 12);
            CP16(dB,              bpH + kt);  CP16(dB + 16,          bpH + kt + 8);
            CP16(dB + BPLANE,     bpL + kt);  CP16(dB + BPLANE + 16, bpL + kt + 8);
            CPC();
            CPW(1);
        } else {
            CPW(0);
        }
        __syncthreads();

        const float* sA = (const float*)(sm + (size_t)cur * FBUF);
        const uint32_t bufB = smb + (uint32_t)cur * FBUF + APLANE;

#pragma unroll
        for (int ks = 0; ks < 2; ks++) {
            const int c0 = ks * 16 + 2 * tg;
            uint32_t ah[2][4], al[2][4];
#pragma unroll
            for (int mf = 0; mf < 2; mf++) {
                const int r0 = warp_m + mf * 16 + g;
                float2 v0 = *(const float2*)&sA[(size_t)r0 * LDAF + c0];
                float2 v1 = *(const float2*)&sA[(size_t)(r0 + 8) * LDAF + c0];
                float2 v2 = *(const float2*)&sA[(size_t)r0 * LDAF + c0 + 8];
                float2 v3 = *(const float2*)&sA[(size_t)(r0 + 8) * LDAF + c0 + 8];
                cvt_pair(v0, ah[mf][0], al[mf][0]);
                cvt_pair(v1, ah[mf][1], al[mf][1]);
                cvt_pair(v2, ah[mf][2], al[mf][2]);
                cvt_pair(v3, ah[mf][3], al[mf][3]);
            }
            uint32_t bh[8][2], bl[8][2];
#pragma unroll
            for (int p = 0; p < 4; p++) {
                ldsm4(bh[2 * p][0], bh[2 * p][1], bh[2 * p + 1][0], bh[2 * p + 1][1],
                      bufB + bLane[p] + ks * 32);
                ldsm4(bl[2 * p][0], bl[2 * p][1], bl[2 * p + 1][0], bl[2 * p + 1][1],
                      bufB + BPLANE + bLane[p] + ks * 32);
            }
#pragma unroll
            for (int nf = 0; nf < 8; nf++) {
                MMA_BF16(acc[0][nf][0], acc[0][nf][1], acc[0][nf][2], acc[0][nf][3],
                         ah[0][0], ah[0][1], ah[0][2], ah[0][3], bh[nf][0], bh[nf][1]);
                MMA_BF16(acc[1][nf][0], acc[1][nf][1], acc[1][nf][2], acc[1][nf][3],
                         ah[1][0], ah[1][1], ah[1][2], ah[1][3], bh[nf][0], bh[nf][1]);
            }
#pragma unroll
            for (int nf = 0; nf < 8; nf++) {
                MMA_BF16(acc[0][nf][0], acc[0][nf][1], acc[0][nf][2], acc[0][nf][3],
                         ah[0][0], ah[0][1], ah[0][2], ah[0][3], bl[nf][0], bl[nf][1]);
                MMA_BF16(acc[1][nf][0], acc[1][nf][1], acc[1][nf][2], acc[1][nf][3],
                         ah[1][0], ah[1][1], ah[1][2], ah[1][3], bl[nf][0], bl[nf][1]);
            }
#pragma unroll
            for (int nf = 0; nf < 8; nf++) {
                MMA_BF16(acc[0][nf][0], acc[0][nf][1], acc[0][nf][2], acc[0][nf][3],
                         al[0][0], al[0][1], al[0][2], al[0][3], bh[nf][0], bh[nf][1]);
                MMA_BF16(acc[1][nf][0], acc[1][nf][1], acc[1][nf][2], acc[1][nf][3],
                         al[1][0], al[1][1], al[1][2], al[1][3], bh[nf][0], bh[nf][1]);
            }
        }
        __syncthreads();
        cur ^= 1;
    }

#pragma unroll
    for (int mf = 0; mf < 2; mf++) {
#pragma unroll
        for (int nf = 0; nf < 8; nf++) {
            const int row0 = blockRow + warp_m + mf * 16 + g;
            const int col = warp_n + nf * 8 + 2 * tg;
            if (row0 < M)
                *(float2*)(C + (size_t)row0 * 128 + col) =
                    make_float2(acc[mf][nf][0], acc[mf][nf][1]);
            if (row0 + 8 < M)
                *(float2*)(C + (size_t)(row0 + 8) * 128 + col) =
                    make_float2(acc[mf][nf][2], acc[mf][nf][3]);
        }
    }
}

// ---------------------------------------------------------------------------
// GEMM2: bf16-plane A (from prop1), KT=128. LDSM fragment loads for A and B.
// ---------------------------------------------------------------------------
#define LDA   40
#define PLANE 10240
#define BUFB  (4 * PLANE)
#define SMEM_GEMM (2 * BUFB)

__global__ __launch_bounds__(256, 2) void tgemm_bf16(
    const __nv_bfloat16* __restrict__ Ahi, const __nv_bfloat16* __restrict__ Alo,
    const __nv_bfloat16* __restrict__ Bhi, const __nv_bfloat16* __restrict__ Blo,
    float* __restrict__ C, int M)
{
    extern __shared__ char sm[];
    const uint32_t smb = smem_u32(sm);
    constexpr int KT = HID;

    const int t = threadIdx.x;
    const int w = t >> 5;
    const int lane = t & 31;
    const int g = lane >> 2;
    const int tg = lane & 3;
    const int warp_m = (w & 3) * 32;
    const int warp_n = (w >> 2) * 64;
    const int blockRow = blockIdx.x * 128;

    // LDSM lane roles
    const int q = lane >> 3;
    const int s8 = lane & 7;
    uint32_t aLane[2];
#pragma unroll
    for (int mf = 0; mf < 2; mf++)
        aLane[mf] = (uint32_t)(warp_m + mf * 16 + ((q & 1) << 3) + s8) * (LDA * 2) + ((q >> 1)) * 16;
    uint32_t bLane[4];
#pragma unroll
    for (int p = 0; p < 4; p++)
        bLane[p] = (uint32_t)(warp_n + p * 16 + ((q >> 1) << 3) + s8) * (LDA * 2) + (q & 1) * 16;

    const int lr = t >> 1;
    const int ko = (t & 1) * 16;
    int grow = blockRow + lr;
    if (grow > M - 1) grow = M - 1;
    const __nv_bfloat16* apH = Ahi + (size_t)grow * KT + ko;
    const __nv_bfloat16* apL = Alo + (size_t)grow * KT + ko;
    const __nv_bfloat16* bpH = Bhi + (size_t)lr * KT + ko;
    const __nv_bfloat16* bpL = Blo + (size_t)lr * KT + ko;
    const uint32_t dstb = smb + lr * 80 + ko * 2;

    float acc[2][8][4];
#pragma unroll
    for (int i = 0; i < 2; i++)
#pragma unroll
        for (int j = 0; j < 8; j++)
#pragma unroll
            for (int k = 0; k < 4; k++) acc[i][j][k] = 0.0f;

    constexpr int NCHUNK = KT / 32;

    {
        const uint32_t db = dstb;
        CP16(db + 0 * PLANE, apH);  CP16(db + 0 * PLANE + 16, apH + 8);
        CP16(db + 1 * PLANE, apL);  CP16(db + 1 * PLANE + 16, apL + 8);
        CP16(db + 2 * PLANE, bpH);  CP16(db + 2 * PLANE + 16, bpH + 8);
        CP16(db + 3 * PLANE, bpL);  CP16(db + 3 * PLANE + 16, bpL + 8);
        CPC();
    }

    int cur = 0;
#pragma unroll 1
    for (int c = 0; c < NCHUNK; c++) {
        if (c + 1 < NCHUNK) {
            const int kt = (c + 1) * 32;
            const uint32_t db = dstb + (cur ^ 1) * BUFB;
            CP16(db + 0 * PLANE, apH + kt);  CP16(db + 0 * PLANE + 16, apH + kt + 8);
            CP16(db + 1 * PLANE, apL + kt);  CP16(db + 1 * PLANE + 16, apL + kt + 8);
            CP16(db + 2 * PLANE, bpH + kt);  CP16(db + 2 * PLANE + 16, bpH + kt + 8);
            CP16(db + 3 * PLANE, bpL + kt);  CP16(db + 3 * PLANE + 16, bpL + kt + 8);
            CPC();
            CPW(1);
        } else {
            CPW(0);
        }
        __syncthreads();

        const uint32_t buf = smb + (uint32_t)cur * BUFB;

#pragma unroll
        for (int ks = 0; ks < 2; ks++) {
            uint32_t ah[2][4], al[2][4];
#pragma unroll
            for (int mf = 0; mf < 2; mf++) {
                ldsm4(ah[mf][0], ah[mf][1], ah[mf][2], ah[mf][3],
                      buf + 0 * PLANE + aLane[mf] + ks * 32);
                ldsm4(al[mf][0], al[mf][1], al[mf][2], al[mf][3],
                      buf + 1 * PLANE + aLane[mf] + ks * 32);
            }
            uint32_t bh[8][2], bl[8][2];
#pragma unroll
            for (int p = 0; p < 4; p++) {
                ldsm4(bh[2 * p][0], bh[2 * p][1], bh[2 * p + 1][0], bh[2 * p + 1][1],
                      buf + 2 * PLANE + bLane[p] + ks * 32);
                ldsm4(bl[2 * p][0], bl[2 * p][1], bl[2 * p + 1][0], bl[2 * p + 1][1],
                      buf + 3 * PLANE + bLane[p] + ks * 32);
            }
#pragma unroll
            for (int nf = 0; nf < 8; nf++) {
                MMA_BF16(acc[0][nf][0], acc[0][nf][1], acc[0][nf][2], acc[0][nf][3],
                         ah[0][0], ah[0][1], ah[0][2], ah[0][3], bh[nf][0], bh[nf][1]);
                MMA_BF16(acc[1][nf][0], acc[1][nf][1], acc[1][nf][2], acc[1][nf][3],
                         ah[1][0], ah[1][1], ah[1][2], ah[1][3], bh[nf][0], bh[nf][1]);
            }
#pragma unroll
            for (int nf = 0; nf < 8; nf++) {
                MMA_BF16(acc[0][nf][0], acc[0][nf][1], acc[0][nf][2], acc[0][nf][3],
                         ah[0][0], ah[0][1], ah[0][2], ah[0][3], bl[nf][0], bl[nf][1]);
                MMA_BF16(acc[1][nf][0], acc[1][nf][1], acc[1][nf][2], acc[1][nf][3],
                         ah[1][0], ah[1][1], ah[1][2], ah[1][3], bl[nf][0], bl[nf][1]);
            }
#pragma unroll
            for (int nf = 0; nf < 8; nf++) {
                MMA_BF16(acc[0][nf][0], acc[0][nf][1], acc[0][nf][2], acc[0][nf][3],
                         al[0][0], al[0][1], al[0][2], al[0][3], bh[nf][0], bh[nf][1]);
                MMA_BF16(acc[1][nf][0], acc[1][nf][1], acc[1][nf][2], acc[1][nf][3],
                         al[1][0], al[1][1], al[1][2], al[1][3], bh[nf][0], bh[nf][1]);
            }
        }
        __syncthreads();
        cur ^= 1;
    }

#pragma unroll
    for (int mf = 0; mf < 2; mf++) {
#pragma unroll
        for (int nf = 0; nf < 8; nf++) {
            const int row0 = blockRow + warp_m + mf * 16 + g;
            const int col = warp_n + nf * 8 + 2 * tg;
            if (row0 < M)
                *(float2*)(C + (size_t)row0 * 128 + col) =
                    make_float2(acc[mf][nf][0], acc[mf][nf][1]);
            if (row0 + 8 < M)
                *(float2*)(C + (size_t)(row0 + 8) * 128 + col) =
                    make_float2(acc[mf][nf][2], acc[mf][nf][3]);
        }
    }
}

// ---------------------------------------------------------------------------
// CSR propagation, 4-way MLP unroll; segments via g_off/g_end
// ---------------------------------------------------------------------------
#define PROP_BODY()                                                              \
    int e = g_off[warp];                                                         \
    const int end = g_end[warp];                                                 \
    for (; e + 4 <= end; e += 4) {                                               \
        int s0 = g_es[e], s1 = g_es[e + 1], s2 = g_es[e + 2], s3 = g_es[e + 3];  \
        float m0 = g_en[e], m1 = g_en[e + 1], m2 = g_en[e + 2], m3 = g_en[e + 3];\
        float4 v0 = ((const float4*)(H + (size_t)s0 * HID))[lane];               \
        float4 v1 = ((const float4*)(H + (size_t)s1 * HID))[lane];               \
        float4 v2 = ((const float4*)(H + (size_t)s2 * HID))[lane];               \
        float4 v3 = ((const float4*)(H + (size_t)s3 * HID))[lane];               \
        ax = fmaf(v0.x, m0, ax); ay = fmaf(v0.y, m0, ay);                        \
        az = fmaf(v0.z, m0, az); aw = fmaf(v0.w, m0, aw);                        \
        ax = fmaf(v1.x, m1, ax); ay = fmaf(v1.y, m1, ay);                        \
        az = fmaf(v1.z, m1, az); aw = fmaf(v1.w, m1, aw);                        \
        ax = fmaf(v2.x, m2, ax); ay = fmaf(v2.y, m2, ay);                        \
        az = fmaf(v2.z, m2, az); aw = fmaf(v2.w, m2, aw);                        \
        ax = fmaf(v3.x, m3, ax); ay = fmaf(v3.y, m3, ay);                        \
        az = fmaf(v3.z, m3, az); aw = fmaf(v3.w, m3, aw);                        \
    }                                                                            \
    for (; e < end; e++) {                                                       \
        int s0 = g_es[e];                                                        \
        float m0 = g_en[e];                                                      \
        float4 v0 = ((const float4*)(H + (size_t)s0 * HID))[lane];               \
        ax = fmaf(v0.x, m0, ax); ay = fmaf(v0.y, m0, ay);                        \
        az = fmaf(v0.z, m0, az); aw = fmaf(v0.w, m0, aw);                        \
    }

__global__ __launch_bounds__(256) void k_prop_csr_split(
    const float* __restrict__ H,
    const float* __restrict__ b)
{
    int warp = (blockIdx.x * blockDim.x + threadIdx.x) >> 5;
    if (warp >= NN) return;
    int lane = threadIdx.x & 31;

    float di = g_dinv[warp];
    float s = di * di;
    float4 bb = ((const float4*)b)[lane];
    float4 v = ((const float4*)(H + (size_t)warp * HID))[lane];
    float ax = fmaf(v.x, s, bb.x);
    float ay = fmaf(v.y, s, bb.y);
    float az = fmaf(v.z, s, bb.z);
    float aw = fmaf(v.w, s, bb.w);

    PROP_BODY()

    ax = fmaxf(ax, 0.f); ay = fmaxf(ay, 0.f);
    az = fmaxf(az, 0.f); aw = fmaxf(aw, 0.f);
    unsigned short h[4], l[4];
    split_bf16(ax, h[0], l[0]); split_bf16(ay, h[1], l[1]);
    split_bf16(az, h[2], l[2]); split_bf16(aw, h[3], l[3]);
    size_t o = (size_t)warp * HID + lane * 4;
    *(uint2*)(g_hhi + o) = make_uint2(h[0] | ((uint32_t)h[1] << 16), h[2] | ((uint32_t)h[3] << 16));
    *(uint2*)(g_hlo + o) = make_uint2(l[0] | ((uint32_t)l[1] << 16), l[2] | ((uint32_t)l[3] << 16));
}

__global__ __launch_bounds__(256) void k_prop_csr_out(
    const float* __restrict__ H,
    const float* __restrict__ bmu,
    const float* __restrict__ blv,
    float* __restrict__ out)
{
    int warp = (blockIdx.x * blockDim.x + threadIdx.x) >> 5;
    if (warp >= NN) return;
    int lane = threadIdx.x & 31;

    float di = g_dinv[warp];
    float s = di * di;
    float4 bb;
    float* dstp;
    if (lane < 16) {
        bb = ((const float4*)bmu)[lane];
        dstp = out + (size_t)warp * 64 + lane * 4;
    } else {
        bb = ((const float4*)blv)[lane - 16];
        dstp = out + (size_t)NN * 64 + (size_t)warp * 64 + (lane - 16) * 4;
    }
    float4 v = ((const float4*)(H + (size_t)warp * HID))[lane];
    float ax = fmaf(v.x, s, bb.x);
    float ay = fmaf(v.y, s, bb.y);
    float az = fmaf(v.z, s, bb.z);
    float aw = fmaf(v.w, s, bb.w);

    PROP_BODY()

    *(float4*)dstp = make_float4(ax, ay, az, aw);
}

// ---------------------------------------------------------------------------
extern "C" void kernel_launch(void* const* d_in, const int* in_sizes, int n_in,
                              void* d_out, int out_size)
{
    const float* x   = (const float*)d_in[0];
    const int*   ei  = (const int*)d_in[1];
    const float* W1  = (const float*)d_in[2];
    const float* b1  = (const float*)d_in[3];
    const float* Wmu = (const float*)d_in[4];
    const float* bmu = (const float*)d_in[5];
    const float* Wlv = (const float*)d_in[6];
    const float* blv = (const float*)d_in[7];
    float* out = (float*)d_out;

    const int* src = ei;
    const int* dst = ei + NE;

    float *h_ptr;
    cudaGetSymbolAddress((void**)&h_ptr, g_h);
    __nv_bfloat16 *hhi, *hlo, *w1hi, *w1lo, *w2hi, *w2lo;
    cudaGetSymbolAddress((void**)&hhi, g_hhi);
    cudaGetSymbolAddress((void**)&hlo, g_hlo);
    cudaGetSymbolAddress((void**)&w1hi, g_w1hi);
    cudaGetSymbolAddress((void**)&w1lo, g_w1lo);
    cudaGetSymbolAddress((void**)&w2hi, g_w2hi);
    cudaGetSymbolAddress((void**)&w2lo, g_w2lo);

    cudaFuncSetAttribute(tgemm_f32a, cudaFuncAttributeMaxDynamicSharedMemorySize, SMEM_F);
    cudaFuncSetAttribute(tgemm_bf16, cudaFuncAttributeMaxDynamicSharedMemorySize, SMEM_GEMM);

    const int TB = 256;

    // Side stream + fork/join events (host-side only; created per call)
    cudaStream_t s2;
    cudaStreamCreateWithFlags(&s2, cudaStreamNonBlocking);
    cudaEvent_t ev_fork, ev_join;
    cudaEventCreateWithFlags(&ev_fork, cudaEventDisableTiming);
    cudaEventCreateWithFlags(&ev_join, cudaEventDisableTiming);

    // --- main stream: W1 conversion (GEMM1 dependency) ---
    k_convw1<<<128, TB>>>(W1);

    // --- fork: CSR build on s2, concurrent with GEMM1 on main ---
    cudaEventRecord(ev_fork, 0);
    cudaStreamWaitEvent(s2, ev_fork, 0);

    k_count_init<<<2564, TB, 0, s2>>>(dst, Wmu, Wlv);
    k_alloc<<<NB, 1024, 0, s2>>>();
    k_scatter<<<(NE + TB - 1) / TB, TB, 0, s2>>>(src, dst);
    cudaEventRecord(ev_join, s2);

    // --- main stream: Layer 1 GEMM ---
    tgemm_f32a<<<(NN + 127) / 128, 256, SMEM_F>>>(x, w1hi, w1lo, h_ptr, NN);

    // --- join: prop1 needs both GEMM1 and CSR ---
    cudaStreamWaitEvent(0, ev_join, 0);

    // --- Propagate + ReLU + split ---
    k_prop_csr_split<<<(NN * 32 + TB - 1) / TB, TB>>>(h_ptr, b1);

    // --- Layer 2: h2 = relu(p) @ [W_mu | W_logvar] ---
    tgemm_bf16<<<(NN + 127) / 128, 256, SMEM_GEMM>>>(hhi, hlo, w2hi, w2lo, h_ptr, NN);

    // --- Propagate to split output ---
    k_prop_csr_out<<<(NN * 32 + TB - 1) / TB, TB>>>(h_ptr, bmu, blv, out);
}

// round 14
// speedup vs baseline: 1.1759x; 1.0482x over previous
#include <cuda_runtime.h>
#include <cuda_bf16.h>
#include <cstdint>

#define NN 100000
#define NE 640000
#define INC 256
#define HID 128
#define NB  ((NN + 1023) / 1024)

// ---------------- scratch (__device__ globals) ----------------
__device__ float g_h[(size_t)NN * HID];
__device__ __nv_bfloat16 g_hhi[(size_t)NN * HID];
__device__ __nv_bfloat16 g_hlo[(size_t)NN * HID];
__device__ __nv_bfloat16 g_w1hi[INC * HID];      // [n=128][k=256]
__device__ __nv_bfloat16 g_w1lo[INC * HID];
__device__ __nv_bfloat16 g_w2hi[HID * HID];      // [n=128][k=128]
__device__ __nv_bfloat16 g_w2lo[HID * HID];
__device__ float g_dinv[NN];
__device__ int   g_cnt[NN];          // zero on entry; re-zeroed by k_alloc
__device__ int   g_off[NN];
__device__ int   g_end[NN];
__device__ int   g_cursor[NN];
__device__ int   g_es[NE];
__device__ float g_en[NE];
__device__ int   g_total;

__device__ __forceinline__ void split_bf16(float x, unsigned short& hi, unsigned short& lo) {
    __nv_bfloat16 h = __float2bfloat16(x);
    float hf = __bfloat162float(h);
    __nv_bfloat16 l = __float2bfloat16(x - hf);
    hi = *reinterpret_cast<unsigned short*>(&h);
    lo = *reinterpret_cast<unsigned short*>(&l);
}

__device__ __forceinline__ void cvt_pair(float2 v, uint32_t& hi, uint32_t& lo) {
    uint32_t x0 = __float_as_uint(v.x), x1 = __float_as_uint(v.y);
    hi = __byte_perm(x0, x1, 0x7632);
    float l0 = v.x - __uint_as_float(x0 & 0xffff0000u);
    float l1 = v.y - __uint_as_float(x1 & 0xffff0000u);
    asm("cvt.rn.bf16x2.f32 %0, %1, %2;" : "=r"(lo) : "f"(l1), "f"(l0));
}

__device__ __forceinline__ uint32_t smem_u32(const void* p) {
    uint32_t a;
    asm("{ .reg .u64 t; cvta.to.shared.u64 t, %1; cvt.u32.u64 %0, t; }" : "=r"(a) : "l"(p));
    return a;
}

__device__ __forceinline__ void ldsm4(uint32_t& d0, uint32_t& d1, uint32_t& d2, uint32_t& d3,
                                      uint32_t addr) {
    asm volatile("ldmatrix.sync.aligned.m8n8.x4.shared.b16 {%0,%1,%2,%3}, [%4];"
                 : "=r"(d0), "=r"(d1), "=r"(d2), "=r"(d3) : "r"(addr));
}

#define CP16(d, s) asm volatile("cp.async.cg.shared.global [%0], [%1], 16;" :: "r"(d), "l"(s) : "memory")
#define CPC()      asm volatile("cp.async.commit_group;" ::: "memory")
#define CPW(n)     asm volatile("cp.async.wait_group %0;" :: "n"(n) : "memory")

#define MMA_BF16(c0,c1,c2,c3,a0,a1,a2,a3,b0,b1)                                  \
    asm volatile("mma.sync.aligned.m16n8k16.row.col.f32.bf16.bf16.f32 "          \
        "{%0,%1,%2,%3}, {%4,%5,%6,%7}, {%8,%9}, {%0,%1,%2,%3};"                  \
        : "+f"(c0), "+f"(c1), "+f"(c2), "+f"(c3)                                  \
        : "r"(a0), "r"(a1), "r"(a2), "r"(a3), "r"(b0), "r"(b1))

// ---------------------------------------------------------------------------
// W1 conversion (must precede GEMM1, main stream)
// ---------------------------------------------------------------------------
__global__ void k_convw1(const float* __restrict__ W1) {
    int i = blockIdx.x * 256 + threadIdx.x;      // i = n*256 + k, 32768 total
    int n = i >> 8, k = i & 255;
    unsigned short h, l;
    split_bf16(W1[k * 128 + n], h, l);
    g_w1hi[i] = *(__nv_bfloat16*)&h;
    g_w1lo[i] = *(__nv_bfloat16*)&l;
}

// ---------------------------------------------------------------------------
// Side-stream: degree count (blocks 0..2499) + convW2 (2500..2563) + reset
// ---------------------------------------------------------------------------
__global__ void k_count_init(const int* __restrict__ dst,
                             const float* __restrict__ Wmu,
                             const float* __restrict__ Wlv)
{
    int b = blockIdx.x;
    int t = threadIdx.x;
    if (b == 0 && t == 0) g_total = 0;
    if (b < 2500) {
        int e = b * 256 + t;                 // NE = 2500*256 exactly
        atomicAdd(&g_cnt[dst[e]], 1);
    } else {
        int i = (b - 2500) * 256 + t;        // i = n*128 + k, 16384 total
        int n = i >> 7, k = i & 127;
        float v = (n < 64) ? Wmu[k * 64 + n] : Wlv[k * 64 + (n - 64)];
        unsigned short h, l;
        split_bf16(v, h, l);
        g_w2hi[i] = *(__nv_bfloat16*)&h;
        g_w2lo[i] = *(__nv_bfloat16*)&l;
    }
}

// ---------------------------------------------------------------------------
// Segment allocation: block-local scan + atomic base grab (+dinv, cnt reset)
// ---------------------------------------------------------------------------
__global__ __launch_bounds__(1024) void k_alloc() {
    __shared__ int sm[1024];
    __shared__ int base;
    const int t = threadIdx.x;
    const int i = blockIdx.x * 1024 + t;
    int v = 0;
    if (i < NN) {
        v = g_cnt[i];
        g_cnt[i] = 0;
        g_dinv[i] = rsqrtf(1.0f + (float)v);
    }
    sm[t] = v;
    __syncthreads();
#pragma unroll
    for (int d = 1; d < 1024; d <<= 1) {
        int x = (t >= d) ? sm[t - d] : 0;
        __syncthreads();
        sm[t] += x;
        __syncthreads();
    }
    if (t == 1023) base = atomicAdd(&g_total, sm[1023]);
    __syncthreads();
    if (i < NN) {
        int off = base + sm[t] - v;
        g_off[i] = off;
        g_end[i] = off + v;
        g_cursor[i] = off;
    }
}

__global__ void k_scatter(const int* __restrict__ src, const int* __restrict__ dst) {
    int e = blockIdx.x * blockDim.x + threadIdx.x;
    if (e >= NE) return;
    int s = src[e], d = dst[e];
    int pos = atomicAdd(&g_cursor[d], 1);
    g_es[pos] = s;
    g_en[pos] = g_dinv[s] * g_dinv[d];
}

// ---------------------------------------------------------------------------
// Shared GEMM geometry: LDA=40 shorts/row (80 B), planes of 128 rows.
// buffer = [AHI | ALO | BHI | BLO], double buffered.
// ---------------------------------------------------------------------------
#define LDA   40
#define PLANE 10240
#define BUFB  (4 * PLANE)
#define SMEM_GEMM (2 * BUFB)

// ---------------------------------------------------------------------------
// GEMM1: C[M,128] = x @ W^T. A arrives fp32; per chunk it is LDG-prefetched
// into registers, split ONCE to bf16 hi/lo, STS'd into smem planes; the
// inner loop is all-LDSM (identical to GEMM2). B via cp.async.
// ---------------------------------------------------------------------------
__global__ __launch_bounds__(256, 2) void tgemm_f32a(
    const float* __restrict__ A,
    const __nv_bfloat16* __restrict__ Bhi, const __nv_bfloat16* __restrict__ Blo,
    float* __restrict__ C, int M)
{
    extern __shared__ char sm[];
    const uint32_t smb = smem_u32(sm);
    constexpr int KT = INC;   // 256

    const int t = threadIdx.x;
    const int w = t >> 5;
    const int lane = t & 31;
    const int g = lane >> 2;
    const int tg = lane & 3;
    const int warp_m = (w & 3) * 32;
    const int warp_n = (w >> 2) * 64;
    const int blockRow = blockIdx.x * 128;

    // LDSM lane roles (same mapping as GEMM2)
    const int q = lane >> 3;
    const int s8 = lane & 7;
    uint32_t aLane[2];
#pragma unroll
    for (int mf = 0; mf < 2; mf++)
        aLane[mf] = (uint32_t)(warp_m + mf * 16 + ((q & 1) << 3) + s8) * (LDA * 2) + ((q >> 1)) * 16;
    uint32_t bLane[4];
#pragma unroll
    for (int p = 0; p < 4; p++)
        bLane[p] = (uint32_t)(warp_n + p * 16 + ((q >> 1) << 3) + s8) * (LDA * 2) + (q & 1) * 16;

    // staging mapping: thread owns row lr, shorts [ko, ko+16) of each chunk
    const int lr = t >> 1;
    const int ko = (t & 1) * 16;
    int grow = blockRow + lr;
    if (grow > M - 1) grow = M - 1;
    const float* ap = A + (size_t)grow * KT + ko;
    const __nv_bfloat16* bpH = Bhi + (size_t)lr * KT + ko;
    const __nv_bfloat16* bpL = Blo + (size_t)lr * KT + ko;
    const uint32_t stOff = (uint32_t)lr * 80 + (uint32_t)ko * 2;   // bytes in plane

    float acc[2][8][4];
#pragma unroll
    for (int i = 0; i < 2; i++)
#pragma unroll
        for (int j = 0; j < 8; j++)
#pragma unroll
            for (int k = 0; k < 4; k++) acc[i][j][k] = 0.0f;

    constexpr int NCHUNK = KT / 32;   // 8

    // prologue: LDG A chunk 0 into regs; cp.async B chunk 0 into buf 0
    float4 ra0 = *(const float4*)(ap);
    float4 ra1 = *(const float4*)(ap + 4);
    float4 ra2 = *(const float4*)(ap + 8);
    float4 ra3 = *(const float4*)(ap + 12);
    {
        const uint32_t dB = smb + stOff;
        CP16(dB + 2 * PLANE, bpH);  CP16(dB + 2 * PLANE + 16, bpH + 8);
        CP16(dB + 3 * PLANE, bpL);  CP16(dB + 3 * PLANE + 16, bpL + 8);
        CPC();
    }

    int cur = 0;
#pragma unroll 1
    for (int c = 0; c < NCHUNK; c++) {
        // ---- convert prefetched A regs once, STS planes into buf[cur] ----
        {
            uint32_t hi[8], lo[8];
            cvt_pair(make_float2(ra0.x, ra0.y), hi[0], lo[0]);
            cvt_pair(make_float2(ra0.z, ra0.w), hi[1], lo[1]);
            cvt_pair(make_float2(ra1.x, ra1.y), hi[2], lo[2]);
            cvt_pair(make_float2(ra1.z, ra1.w), hi[3], lo[3]);
            cvt_pair(make_float2(ra2.x, ra2.y), hi[4], lo[4]);
            cvt_pair(make_float2(ra2.z, ra2.w), hi[5], lo[5]);
            cvt_pair(make_float2(ra3.x, ra3.y), hi[6], lo[6]);
            cvt_pair(make_float2(ra3.z, ra3.w), hi[7], lo[7]);
            char* base = sm + (size_t)cur * BUFB + stOff;
            *(uint4*)(base)              = make_uint4(hi[0], hi[1], hi[2], hi[3]);
            *(uint4*)(base + 16)         = make_uint4(hi[4], hi[5], hi[6], hi[7]);
            *(uint4*)(base + PLANE)      = make_uint4(lo[0], lo[1], lo[2], lo[3]);
            *(uint4*)(base + PLANE + 16) = make_uint4(lo[4], lo[5], lo[6], lo[7]);
        }
        // ---- prefetch next chunk (A regs + B cp.async) ----
        if (c + 1 < NCHUNK) {
            const int kt = (c + 1) * 32;
            ra0 = *(const float4*)(ap + kt);
            ra1 = *(const float4*)(ap + kt + 4);
            ra2 = *(const float4*)(ap + kt + 8);
            ra3 = *(const float4*)(ap + kt + 12);
            const uint32_t dB = smb + (cur ^ 1) * BUFB + stOff;
            CP16(dB + 2 * PLANE, bpH + kt);  CP16(dB + 2 * PLANE + 16, bpH + kt + 8);
            CP16(dB + 3 * PLANE, bpL + kt);  CP16(dB + 3 * PLANE + 16, bpL + kt + 8);
            CPC();
            CPW(1);
        } else {
            CPW(0);
        }
        __syncthreads();

        const uint32_t buf = smb + (uint32_t)cur * BUFB;

#pragma unroll
        for (int ks = 0; ks < 2; ks++) {
            uint32_t ah[2][4], al[2][4];
#pragma unroll
            for (int mf = 0; mf < 2; mf++) {
                ldsm4(ah[mf][0], ah[mf][1], ah[mf][2], ah[mf][3],
                      buf + 0 * PLANE + aLane[mf] + ks * 32);
                ldsm4(al[mf][0], al[mf][1], al[mf][2], al[mf][3],
                      buf + 1 * PLANE + aLane[mf] + ks * 32);
            }
            uint32_t bh[8][2], bl[8][2];
#pragma unroll
            for (int p = 0; p < 4; p++) {
                ldsm4(bh[2 * p][0], bh[2 * p][1], bh[2 * p + 1][0], bh[2 * p + 1][1],
                      buf + 2 * PLANE + bLane[p] + ks * 32);
                ldsm4(bl[2 * p][0], bl[2 * p][1], bl[2 * p + 1][0], bl[2 * p + 1][1],
                      buf + 3 * PLANE + bLane[p] + ks * 32);
            }
#pragma unroll
            for (int nf = 0; nf < 8; nf++) {
                MMA_BF16(acc[0][nf][0], acc[0][nf][1], acc[0][nf][2], acc[0][nf][3],
                         ah[0][0], ah[0][1], ah[0][2], ah[0][3], bh[nf][0], bh[nf][1]);
                MMA_BF16(acc[1][nf][0], acc[1][nf][1], acc[1][nf][2], acc[1][nf][3],
                         ah[1][0], ah[1][1], ah[1][2], ah[1][3], bh[nf][0], bh[nf][1]);
            }
#pragma unroll
            for (int nf = 0; nf < 8; nf++) {
                MMA_BF16(acc[0][nf][0], acc[0][nf][1], acc[0][nf][2], acc[0][nf][3],
                         ah[0][0], ah[0][1], ah[0][2], ah[0][3], bl[nf][0], bl[nf][1]);
                MMA_BF16(acc[1][nf][0], acc[1][nf][1], acc[1][nf][2], acc[1][nf][3],
                         ah[1][0], ah[1][1], ah[1][2], ah[1][3], bl[nf][0], bl[nf][1]);
            }
#pragma unroll
            for (int nf = 0; nf < 8; nf++) {
                MMA_BF16(acc[0][nf][0], acc[0][nf][1], acc[0][nf][2], acc[0][nf][3],
                         al[0][0], al[0][1], al[0][2], al[0][3], bh[nf][0], bh[nf][1]);
                MMA_BF16(acc[1][nf][0], acc[1][nf][1], acc[1][nf][2], acc[1][nf][3],
                         al[1][0], al[1][1], al[1][2], al[1][3], bh[nf][0], bh[nf][1]);
            }
        }
        __syncthreads();
        cur ^= 1;
    }

#pragma unroll
    for (int mf = 0; mf < 2; mf++) {
#pragma unroll
        for (int nf = 0; nf < 8; nf++) {
            const int row0 = blockRow + warp_m + mf * 16 + g;
            const int col = warp_n + nf * 8 + 2 * tg;
            if (row0 < M)
                *(float2*)(C + (size_t)row0 * 128 + col) =
                    make_float2(acc[mf][nf][0], acc[mf][nf][1]);
            if (row0 + 8 < M)
                *(float2*)(C + (size_t)(row0 + 8) * 128 + col) =
                    make_float2(acc[mf][nf][2], acc[mf][nf][3]);
        }
    }
}

// ---------------------------------------------------------------------------
// GEMM2: bf16-plane A (from prop1), KT=128. LDSM fragment loads for A and B.
// (unchanged from R13)
// ---------------------------------------------------------------------------
__global__ __launch_bounds__(256, 2) void tgemm_bf16(
    const __nv_bfloat16* __restrict__ Ahi, const __nv_bfloat16* __restrict__ Alo,
    const __nv_bfloat16* __restrict__ Bhi, const __nv_bfloat16* __restrict__ Blo,
    float* __restrict__ C, int M)
{
    extern __shared__ char sm[];
    const uint32_t smb = smem_u32(sm);
    constexpr int KT = HID;

    const int t = threadIdx.x;
    const int w = t >> 5;
    const int lane = t & 31;
    const int g = lane >> 2;
    const int tg = lane & 3;
    const int warp_m = (w & 3) * 32;
    const int warp_n = (w >> 2) * 64;
    const int blockRow = blockIdx.x * 128;

    const int q = lane >> 3;
    const int s8 = lane & 7;
    uint32_t aLane[2];
#pragma unroll
    for (int mf = 0; mf < 2; mf++)
        aLane[mf] = (uint32_t)(warp_m + mf * 16 + ((q & 1) << 3) + s8) * (LDA * 2) + ((q >> 1)) * 16;
    uint32_t bLane[4];
#pragma unroll
    for (int p = 0; p < 4; p++)
        bLane[p] = (uint32_t)(warp_n + p * 16 + ((q >> 1) << 3) + s8) * (LDA * 2) + (q & 1) * 16;

    const int lr = t >> 1;
    const int ko = (t & 1) * 16;
    int grow = blockRow + lr;
    if (grow > M - 1) grow = M - 1;
    const __nv_bfloat16* apH = Ahi + (size_t)grow * KT + ko;
    const __nv_bfloat16* apL = Alo + (size_t)grow * KT + ko;
    const __nv_bfloat16* bpH = Bhi + (size_t)lr * KT + ko;
    const __nv_bfloat16* bpL = Blo + (size_t)lr * KT + ko;
    const uint32_t dstb = smb + lr * 80 + ko * 2;

    float acc[2][8][4];
#pragma unroll
    for (int i = 0; i < 2; i++)
#pragma unroll
        for (int j = 0; j < 8; j++)
#pragma unroll
            for (int k = 0; k < 4; k++) acc[i][j][k] = 0.0f;

    constexpr int NCHUNK = KT / 32;

    {
        const uint32_t db = dstb;
        CP16(db + 0 * PLANE, apH);  CP16(db + 0 * PLANE + 16, apH + 8);
        CP16(db + 1 * PLANE, apL);  CP16(db + 1 * PLANE + 16, apL + 8);
        CP16(db + 2 * PLANE, bpH);  CP16(db + 2 * PLANE + 16, bpH + 8);
        CP16(db + 3 * PLANE, bpL);  CP16(db + 3 * PLANE + 16, bpL + 8);
        CPC();
    }

    int cur = 0;
#pragma unroll 1
    for (int c = 0; c < NCHUNK; c++) {
        if (c + 1 < NCHUNK) {
            const int kt = (c + 1) * 32;
            const uint32_t db = dstb + (cur ^ 1) * BUFB;
            CP16(db + 0 * PLANE, apH + kt);  CP16(db + 0 * PLANE + 16, apH + kt + 8);
            CP16(db + 1 * PLANE, apL + kt);  CP16(db + 1 * PLANE + 16, apL + kt + 8);
            CP16(db + 2 * PLANE, bpH + kt);  CP16(db + 2 * PLANE + 16, bpH + kt + 8);
            CP16(db + 3 * PLANE, bpL + kt);  CP16(db + 3 * PLANE + 16, bpL + kt + 8);
            CPC();
            CPW(1);
        } else {
            CPW(0);
        }
        __syncthreads();

        const uint32_t buf = smb + (uint32_t)cur * BUFB;

#pragma unroll
        for (int ks = 0; ks < 2; ks++) {
            uint32_t ah[2][4], al[2][4];
#pragma unroll
            for (int mf = 0; mf < 2; mf++) {
                ldsm4(ah[mf][0], ah[mf][1], ah[mf][2], ah[mf][3],
                      buf + 0 * PLANE + aLane[mf] + ks * 32);
                ldsm4(al[mf][0], al[mf][1], al[mf][2], al[mf][3],
                      buf + 1 * PLANE + aLane[mf] + ks * 32);
            }
            uint32_t bh[8][2], bl[8][2];
#pragma unroll
            for (int p = 0; p < 4; p++) {
                ldsm4(bh[2 * p][0], bh[2 * p][1], bh[2 * p + 1][0], bh[2 * p + 1][1],
                      buf + 2 * PLANE + bLane[p] + ks * 32);
                ldsm4(bl[2 * p][0], bl[2 * p][1], bl[2 * p + 1][0], bl[2 * p + 1][1],
                      buf + 3 * PLANE + bLane[p] + ks * 32);
            }
#pragma unroll
            for (int nf = 0; nf < 8; nf++) {
                MMA_BF16(acc[0][nf][0], acc[0][nf][1], acc[0][nf][2], acc[0][nf][3],
                         ah[0][0], ah[0][1], ah[0][2], ah[0][3], bh[nf][0], bh[nf][1]);
                MMA_BF16(acc[1][nf][0], acc[1][nf][1], acc[1][nf][2], acc[1][nf][3],
                         ah[1][0], ah[1][1], ah[1][2], ah[1][3], bh[nf][0], bh[nf][1]);
            }
#pragma unroll
            for (int nf = 0; nf < 8; nf++) {
                MMA_BF16(acc[0][nf][0], acc[0][nf][1], acc[0][nf][2], acc[0][nf][3],
                         ah[0][0], ah[0][1], ah[0][2], ah[0][3], bl[nf][0], bl[nf][1]);
                MMA_BF16(acc[1][nf][0], acc[1][nf][1], acc[1][nf][2], acc[1][nf][3],
                         ah[1][0], ah[1][1], ah[1][2], ah[1][3], bl[nf][0], bl[nf][1]);
            }
#pragma unroll
            for (int nf = 0; nf < 8; nf++) {
                MMA_BF16(acc[0][nf][0], acc[0][nf][1], acc[0][nf][2], acc[0][nf][3],
                         al[0][0], al[0][1], al[0][2], al[0][3], bh[nf][0], bh[nf][1]);
                MMA_BF16(acc[1][nf][0], acc[1][nf][1], acc[1][nf][2], acc[1][nf][3],
                         al[1][0], al[1][1], al[1][2], al[1][3], bh[nf][0], bh[nf][1]);
            }
        }
        __syncthreads();
        cur ^= 1;
    }

#pragma unroll
    for (int mf = 0; mf < 2; mf++) {
#pragma unroll
        for (int nf = 0; nf < 8; nf++) {
            const int row0 = blockRow + warp_m + mf * 16 + g;
            const int col = warp_n + nf * 8 + 2 * tg;
            if (row0 < M)
                *(float2*)(C + (size_t)row0 * 128 + col) =
                    make_float2(acc[mf][nf][0], acc[mf][nf][1]);
            if (row0 + 8 < M)
                *(float2*)(C + (size_t)(row0 + 8) * 128 + col) =
                    make_float2(acc[mf][nf][2], acc[mf][nf][3]);
        }
    }
}

// ---------------------------------------------------------------------------
// CSR propagation, 4-way MLP unroll; segments via g_off/g_end
// ---------------------------------------------------------------------------
#define PROP_BODY()                                                              \
    int e = g_off[warp];                                                         \
    const int end = g_end[warp];                                                 \
    for (; e + 4 <= end; e += 4) {                                               \
        int s0 = g_es[e], s1 = g_es[e + 1], s2 = g_es[e + 2], s3 = g_es[e + 3];  \
        float m0 = g_en[e], m1 = g_en[e + 1], m2 = g_en[e + 2], m3 = g_en[e + 3];\
        float4 v0 = ((const float4*)(H + (size_t)s0 * HID))[lane];               \
        float4 v1 = ((const float4*)(H + (size_t)s1 * HID))[lane];               \
        float4 v2 = ((const float4*)(H + (size_t)s2 * HID))[lane];               \
        float4 v3 = ((const float4*)(H + (size_t)s3 * HID))[lane];               \
        ax = fmaf(v0.x, m0, ax); ay = fmaf(v0.y, m0, ay);                        \
        az = fmaf(v0.z, m0, az); aw = fmaf(v0.w, m0, aw);                        \
        ax = fmaf(v1.x, m1, ax); ay = fmaf(v1.y, m1, ay);                        \
        az = fmaf(v1.z, m1, az); aw = fmaf(v1.w, m1, aw);                        \
        ax = fmaf(v2.x, m2, ax); ay = fmaf(v2.y, m2, ay);                        \
        az = fmaf(v2.z, m2, az); aw = fmaf(v2.w, m2, aw);                        \
        ax = fmaf(v3.x, m3, ax); ay = fmaf(v3.y, m3, ay);                        \
        az = fmaf(v3.z, m3, az); aw = fmaf(v3.w, m3, aw);                        \
    }                                                                            \
    for (; e < end; e++) {                                                       \
        int s0 = g_es[e];                                                        \
        float m0 = g_en[e];                                                      \
        float4 v0 = ((const float4*)(H + (size_t)s0 * HID))[lane];               \
        ax = fmaf(v0.x, m0, ax); ay = fmaf(v0.y, m0, ay);                        \
        az = fmaf(v0.z, m0, az); aw = fmaf(v0.w, m0, aw);                        \
    }

__global__ __launch_bounds__(256) void k_prop_csr_split(
    const float* __restrict__ H,
    const float* __restrict__ b)
{
    int warp = (blockIdx.x * blockDim.x + threadIdx.x) >> 5;
    if (warp >= NN) return;
    int lane = threadIdx.x & 31;

    float di = g_dinv[warp];
    float s = di * di;
    float4 bb = ((const float4*)b)[lane];
    float4 v = ((const float4*)(H + (size_t)warp * HID))[lane];
    float ax = fmaf(v.x, s, bb.x);
    float ay = fmaf(v.y, s, bb.y);
    float az = fmaf(v.z, s, bb.z);
    float aw = fmaf(v.w, s, bb.w);

    PROP_BODY()

    ax = fmaxf(ax, 0.f); ay = fmaxf(ay, 0.f);
    az = fmaxf(az, 0.f); aw = fmaxf(aw, 0.f);
    unsigned short h[4], l[4];
    split_bf16(ax, h[0], l[0]); split_bf16(ay, h[1], l[1]);
    split_bf16(az, h[2], l[2]); split_bf16(aw, h[3], l[3]);
    size_t o = (size_t)warp * HID + lane * 4;
    *(uint2*)(g_hhi + o) = make_uint2(h[0] | ((uint32_t)h[1] << 16), h[2] | ((uint32_t)h[3] << 16));
    *(uint2*)(g_hlo + o) = make_uint2(l[0] | ((uint32_t)l[1] << 16), l[2] | ((uint32_t)l[3] << 16));
}

__global__ __launch_bounds__(256) void k_prop_csr_out(
    const float* __restrict__ H,
    const float* __restrict__ bmu,
    const float* __restrict__ blv,
    float* __restrict__ out)
{
    int warp = (blockIdx.x * blockDim.x + threadIdx.x) >> 5;
    if (warp >= NN) return;
    int lane = threadIdx.x & 31;

    float di = g_dinv[warp];
    float s = di * di;
    float4 bb;
    float* dstp;
    if (lane < 16) {
        bb = ((const float4*)bmu)[lane];
        dstp = out + (size_t)warp * 64 + lane * 4;
    } else {
        bb = ((const float4*)blv)[lane - 16];
        dstp = out + (size_t)NN * 64 + (size_t)warp * 64 + (lane - 16) * 4;
    }
    float4 v = ((const float4*)(H + (size_t)warp * HID))[lane];
    float ax = fmaf(v.x, s, bb.x);
    float ay = fmaf(v.y, s, bb.y);
    float az = fmaf(v.z, s, bb.z);
    float aw = fmaf(v.w, s, bb.w);

    PROP_BODY()

    *(float4*)dstp = make_float4(ax, ay, az, aw);
}

// ---------------------------------------------------------------------------
extern "C" void kernel_launch(void* const* d_in, const int* in_sizes, int n_in,
                              void* d_out, int out_size)
{
    const float* x   = (const float*)d_in[0];
    const int*   ei  = (const int*)d_in[1];
    const float* W1  = (const float*)d_in[2];
    const float* b1  = (const float*)d_in[3];
    const float* Wmu = (const float*)d_in[4];
    const float* bmu = (const float*)d_in[5];
    const float* Wlv = (const float*)d_in[6];
    const float* blv = (const float*)d_in[7];
    float* out = (float*)d_out;

    const int* src = ei;
    const int* dst = ei + NE;

    float *h_ptr;
    cudaGetSymbolAddress((void**)&h_ptr, g_h);
    __nv_bfloat16 *hhi, *hlo, *w1hi, *w1lo, *w2hi, *w2lo;
    cudaGetSymbolAddress((void**)&hhi, g_hhi);
    cudaGetSymbolAddress((void**)&hlo, g_hlo);
    cudaGetSymbolAddress((void**)&w1hi, g_w1hi);
    cudaGetSymbolAddress((void**)&w1lo, g_w1lo);
    cudaGetSymbolAddress((void**)&w2hi, g_w2hi);
    cudaGetSymbolAddress((void**)&w2lo, g_w2lo);

    cudaFuncSetAttribute(tgemm_f32a, cudaFuncAttributeMaxDynamicSharedMemorySize, SMEM_GEMM);
    cudaFuncSetAttribute(tgemm_bf16, cudaFuncAttributeMaxDynamicSharedMemorySize, SMEM_GEMM);

    const int TB = 256;

    // Side stream + fork/join events (host-side only; created per call)
    cudaStream_t s2;
    cudaStreamCreateWithFlags(&s2, cudaStreamNonBlocking);
    cudaEvent_t ev_fork, ev_join;
    cudaEventCreateWithFlags(&ev_fork, cudaEventDisableTiming);
    cudaEventCreateWithFlags(&ev_join, cudaEventDisableTiming);

    // --- main stream: W1 conversion (GEMM1 dependency) ---
    k_convw1<<<128, TB>>>(W1);

    // --- fork: CSR build on s2, concurrent with GEMM1 on main ---
    cudaEventRecord(ev_fork, 0);
    cudaStreamWaitEvent(s2, ev_fork, 0);

    k_count_init<<<2564, TB, 0, s2>>>(dst, Wmu, Wlv);
    k_alloc<<<NB, 1024, 0, s2>>>();
    k_scatter<<<(NE + TB - 1) / TB, TB, 0, s2>>>(src, dst);
    cudaEventRecord(ev_join, s2);

    // --- main stream: Layer 1 GEMM ---
    tgemm_f32a<<<(NN + 127) / 128, 256, SMEM_GEMM>>>(x, w1hi, w1lo, h_ptr, NN);

    // --- join: prop1 needs both GEMM1 and CSR ---
    cudaStreamWaitEvent(0, ev_join, 0);

    // --- Propagate + ReLU + split ---
    k_prop_csr_split<<<(NN * 32 + TB - 1) / TB, TB>>>(h_ptr, b1);

    // --- Layer 2: h2 = relu(p) @ [W_mu | W_logvar] ---
    tgemm_bf16<<<(NN + 127) / 128, 256, SMEM_GEMM>>>(hhi, hlo, w2hi, w2lo, h_ptr, NN);

    // --- Propagate to split output ---
    k_prop_csr_out<<<(NN * 32 + TB - 1) / TB, TB>>>(h_ptr, bmu, blv, out);
}

// round 15
// speedup vs baseline: 1.3393x; 1.1390x over previous
#include <cuda_runtime.h>
#include <cuda_fp16.h>
#include <cstdint>

#define NN 100000
#define NE 640000
#define INC 256
#define HID 128
#define NB  ((NN + 1023) / 1024)

// ---------------- scratch (__device__ globals) ----------------
__device__ float g_h[(size_t)NN * HID];
__device__ unsigned short g_hh[(size_t)NN * HID];     // fp16 relu(p) (single plane)
__device__ unsigned short g_w1hi[INC * HID];          // [n=128][k=256] fp16
__device__ unsigned short g_w1lo[INC * HID];
__device__ unsigned short g_w2hi[HID * HID];          // [n=128][k=128] fp16
__device__ unsigned short g_w2lo[HID * HID];
__device__ float g_dinv[NN];
__device__ int   g_cnt[NN];          // zero on entry; re-zeroed by k_alloc
__device__ int   g_off[NN];
__device__ int   g_end[NN];
__device__ int   g_cursor[NN];
__device__ int   g_es[NE];
__device__ float g_en[NE];
__device__ int   g_total;

__device__ __forceinline__ void split_f16(float x, unsigned short& hi, unsigned short& lo) {
    __half h = __float2half_rn(x);
    float hf = __half2float(h);
    __half l = __float2half_rn(x - hf);
    hi = *reinterpret_cast<unsigned short*>(&h);
    lo = *reinterpret_cast<unsigned short*>(&l);
}

// pack two floats into one f16x2 word: .lo = a, .hi = b
__device__ __forceinline__ uint32_t pack_h2(float a, float b) {
    uint32_t r;
    asm("cvt.rn.f16x2.f32 %0, %1, %2;" : "=r"(r) : "f"(b), "f"(a));
    return r;
}

__device__ __forceinline__ uint32_t smem_u32(const void* p) {
    uint32_t a;
    asm("{ .reg .u64 t; cvta.to.shared.u64 t, %1; cvt.u32.u64 %0, t; }" : "=r"(a) : "l"(p));
    return a;
}

__device__ __forceinline__ void ldsm4(uint32_t& d0, uint32_t& d1, uint32_t& d2, uint32_t& d3,
                                      uint32_t addr) {
    asm volatile("ldmatrix.sync.aligned.m8n8.x4.shared.b16 {%0,%1,%2,%3}, [%4];"
                 : "=r"(d0), "=r"(d1), "=r"(d2), "=r"(d3) : "r"(addr));
}

#define CP16(d, s) asm volatile("cp.async.cg.shared.global [%0], [%1], 16;" :: "r"(d), "l"(s) : "memory")
#define CPC()      asm volatile("cp.async.commit_group;" ::: "memory")
#define CPW(n)     asm volatile("cp.async.wait_group %0;" :: "n"(n) : "memory")

#define MMA_F16(c0,c1,c2,c3,a0,a1,a2,a3,b0,b1)                                   \
    asm volatile("mma.sync.aligned.m16n8k16.row.col.f32.f16.f16.f32 "            \
        "{%0,%1,%2,%3}, {%4,%5,%6,%7}, {%8,%9}, {%0,%1,%2,%3};"                  \
        : "+f"(c0), "+f"(c1), "+f"(c2), "+f"(c3)                                  \
        : "r"(a0), "r"(a1), "r"(a2), "r"(a3), "r"(b0), "r"(b1))

// ---------------------------------------------------------------------------
// W1 conversion (must precede GEMM1, main stream)
// ---------------------------------------------------------------------------
__global__ void k_convw1(const float* __restrict__ W1) {
    int i = blockIdx.x * 256 + threadIdx.x;      // i = n*256 + k, 32768 total
    int n = i >> 8, k = i & 255;
    unsigned short h, l;
    split_f16(W1[k * 128 + n], h, l);
    g_w1hi[i] = h;
    g_w1lo[i] = l;
}

// ---------------------------------------------------------------------------
// Side-stream: degree count (blocks 0..2499) + convW2 (2500..2563) + reset
// ---------------------------------------------------------------------------
__global__ void k_count_init(const int* __restrict__ dst,
                             const float* __restrict__ Wmu,
                             const float* __restrict__ Wlv)
{
    int b = blockIdx.x;
    int t = threadIdx.x;
    if (b == 0 && t == 0) g_total = 0;
    if (b < 2500) {
        int e = b * 256 + t;                 // NE = 2500*256 exactly
        atomicAdd(&g_cnt[dst[e]], 1);
    } else {
        int i = (b - 2500) * 256 + t;        // i = n*128 + k, 16384 total
        int n = i >> 7, k = i & 127;
        float v = (n < 64) ? Wmu[k * 64 + n] : Wlv[k * 64 + (n - 64)];
        unsigned short h, l;
        split_f16(v, h, l);
        g_w2hi[i] = h;
        g_w2lo[i] = l;
    }
}

// ---------------------------------------------------------------------------
// Segment allocation: block-local scan + atomic base grab (+dinv, cnt reset)
// ---------------------------------------------------------------------------
__global__ __launch_bounds__(1024) void k_alloc() {
    __shared__ int sm[1024];
    __shared__ int base;
    const int t = threadIdx.x;
    const int i = blockIdx.x * 1024 + t;
    int v = 0;
    if (i < NN) {
        v = g_cnt[i];
        g_cnt[i] = 0;
        g_dinv[i] = rsqrtf(1.0f + (float)v);
    }
    sm[t] = v;
    __syncthreads();
#pragma unroll
    for (int d = 1; d < 1024; d <<= 1) {
        int x = (t >= d) ? sm[t - d] : 0;
        __syncthreads();
        sm[t] += x;
        __syncthreads();
    }
    if (t == 1023) base = atomicAdd(&g_total, sm[1023]);
    __syncthreads();
    if (i < NN) {
        int off = base + sm[t] - v;
        g_off[i] = off;
        g_end[i] = off + v;
        g_cursor[i] = off;
    }
}

__global__ void k_scatter(const int* __restrict__ src, const int* __restrict__ dst) {
    int e = blockIdx.x * blockDim.x + threadIdx.x;
    if (e >= NE) return;
    int s = src[e], d = dst[e];
    int pos = atomicAdd(&g_cursor[d], 1);
    g_es[pos] = s;
    g_en[pos] = g_dinv[s] * g_dinv[d];
}

// ---------------------------------------------------------------------------
// Shared GEMM geometry: LDA=40 shorts/row (80 B), planes of 128 rows.
// buffer = [A | BHI | BLO], double buffered. 2-pass fp16: a*bh + a*bl.
// ---------------------------------------------------------------------------
#define LDA   40
#define PLANE 10240
#define BUF3  (3 * PLANE)
#define SMEM_GEMM (2 * BUF3)

// ---------------------------------------------------------------------------
// GEMM1: C[M,128] = x @ W^T. A fp32 LDG-prefetched, converted once to fp16
// (single plane), STS; inner loop all-LDSM. B (fp16 hi/lo) via cp.async.
// ---------------------------------------------------------------------------
__global__ __launch_bounds__(256, 2) void tgemm_f32a(
    const float* __restrict__ A,
    const unsigned short* __restrict__ Bhi, const unsigned short* __restrict__ Blo,
    float* __restrict__ C, int M)
{
    extern __shared__ char sm[];
    const uint32_t smb = smem_u32(sm);
    constexpr int KT = INC;   // 256

    const int t = threadIdx.x;
    const int w = t >> 5;
    const int lane = t & 31;
    const int g = lane >> 2;
    const int tg = lane & 3;
    const int warp_m = (w & 3) * 32;
    const int warp_n = (w >> 2) * 64;
    const int blockRow = blockIdx.x * 128;

    const int q = lane >> 3;
    const int s8 = lane & 7;
    uint32_t aLane[2];
#pragma unroll
    for (int mf = 0; mf < 2; mf++)
        aLane[mf] = (uint32_t)(warp_m + mf * 16 + ((q & 1) << 3) + s8) * (LDA * 2) + ((q >> 1)) * 16;
    uint32_t bLane[4];
#pragma unroll
    for (int p = 0; p < 4; p++)
        bLane[p] = (uint32_t)(warp_n + p * 16 + ((q >> 1) << 3) + s8) * (LDA * 2) + (q & 1) * 16;

    const int lr = t >> 1;
    const int ko = (t & 1) * 16;
    int grow = blockRow + lr;
    if (grow > M - 1) grow = M - 1;
    const float* ap = A + (size_t)grow * KT + ko;
    const unsigned short* bpH = Bhi + (size_t)lr * KT + ko;
    const unsigned short* bpL = Blo + (size_t)lr * KT + ko;
    const uint32_t stOff = (uint32_t)lr * 80 + (uint32_t)ko * 2;

    float acc[2][8][4];
#pragma unroll
    for (int i = 0; i < 2; i++)
#pragma unroll
        for (int j = 0; j < 8; j++)
#pragma unroll
            for (int k = 0; k < 4; k++) acc[i][j][k] = 0.0f;

    constexpr int NCHUNK = KT / 32;   // 8

    // prologue: LDG A chunk 0 into regs; cp.async B chunk 0 into buf 0
    float4 ra0 = *(const float4*)(ap);
    float4 ra1 = *(const float4*)(ap + 4);
    float4 ra2 = *(const float4*)(ap + 8);
    float4 ra3 = *(const float4*)(ap + 12);
    {
        const uint32_t dB = smb + stOff;
        CP16(dB + 1 * PLANE, bpH);  CP16(dB + 1 * PLANE + 16, bpH + 8);
        CP16(dB + 2 * PLANE, bpL);  CP16(dB + 2 * PLANE + 16, bpL + 8);
        CPC();
    }

    int cur = 0;
#pragma unroll 1
    for (int c = 0; c < NCHUNK; c++) {
        // ---- convert prefetched A regs once (fp16), STS single plane ----
        {
            uint32_t p0 = pack_h2(ra0.x, ra0.y);
            uint32_t p1 = pack_h2(ra0.z, ra0.w);
            uint32_t p2 = pack_h2(ra1.x, ra1.y);
            uint32_t p3 = pack_h2(ra1.z, ra1.w);
            uint32_t p4 = pack_h2(ra2.x, ra2.y);
            uint32_t p5 = pack_h2(ra2.z, ra2.w);
            uint32_t p6 = pack_h2(ra3.x, ra3.y);
            uint32_t p7 = pack_h2(ra3.z, ra3.w);
            char* base = sm + (size_t)cur * BUF3 + stOff;
            *(uint4*)(base)      = make_uint4(p0, p1, p2, p3);
            *(uint4*)(base + 16) = make_uint4(p4, p5, p6, p7);
        }
        // ---- prefetch next chunk (A regs + B cp.async) ----
        if (c + 1 < NCHUNK) {
            const int kt = (c + 1) * 32;
            ra0 = *(const float4*)(ap + kt);
            ra1 = *(const float4*)(ap + kt + 4);
            ra2 = *(const float4*)(ap + kt + 8);
            ra3 = *(const float4*)(ap + kt + 12);
            const uint32_t dB = smb + (cur ^ 1) * BUF3 + stOff;
            CP16(dB + 1 * PLANE, bpH + kt);  CP16(dB + 1 * PLANE + 16, bpH + kt + 8);
            CP16(dB + 2 * PLANE, bpL + kt);  CP16(dB + 2 * PLANE + 16, bpL + kt + 8);
            CPC();
            CPW(1);
        } else {
            CPW(0);
        }
        __syncthreads();

        const uint32_t buf = smb + (uint32_t)cur * BUF3;

#pragma unroll
        for (int ks = 0; ks < 2; ks++) {
            uint32_t ah[2][4];
#pragma unroll
            for (int mf = 0; mf < 2; mf++)
                ldsm4(ah[mf][0], ah[mf][1], ah[mf][2], ah[mf][3],
                      buf + aLane[mf] + ks * 32);
            uint32_t bh[8][2], bl[8][2];
#pragma unroll
            for (int p = 0; p < 4; p++) {
                ldsm4(bh[2 * p][0], bh[2 * p][1], bh[2 * p + 1][0], bh[2 * p + 1][1],
                      buf + 1 * PLANE + bLane[p] + ks * 32);
                ldsm4(bl[2 * p][0], bl[2 * p][1], bl[2 * p + 1][0], bl[2 * p + 1][1],
                      buf + 2 * PLANE + bLane[p] + ks * 32);
            }
#pragma unroll
            for (int nf = 0; nf < 8; nf++) {
                MMA_F16(acc[0][nf][0], acc[0][nf][1], acc[0][nf][2], acc[0][nf][3],
                        ah[0][0], ah[0][1], ah[0][2], ah[0][3], bh[nf][0], bh[nf][1]);
                MMA_F16(acc[1][nf][0], acc[1][nf][1], acc[1][nf][2], acc[1][nf][3],
                        ah[1][0], ah[1][1], ah[1][2], ah[1][3], bh[nf][0], bh[nf][1]);
            }
#pragma unroll
            for (int nf = 0; nf < 8; nf++) {
                MMA_F16(acc[0][nf][0], acc[0][nf][1], acc[0][nf][2], acc[0][nf][3],
                        ah[0][0], ah[0][1], ah[0][2], ah[0][3], bl[nf][0], bl[nf][1]);
                MMA_F16(acc[1][nf][0], acc[1][nf][1], acc[1][nf][2], acc[1][nf][3],
                        ah[1][0], ah[1][1], ah[1][2], ah[1][3], bl[nf][0], bl[nf][1]);
            }
        }
        __syncthreads();
        cur ^= 1;
    }

#pragma unroll
    for (int mf = 0; mf < 2; mf++) {
#pragma unroll
        for (int nf = 0; nf < 8; nf++) {
            const int row0 = blockRow + warp_m + mf * 16 + g;
            const int col = warp_n + nf * 8 + 2 * tg;
            if (row0 < M)
                *(float2*)(C + (size_t)row0 * 128 + col) =
                    make_float2(acc[mf][nf][0], acc[mf][nf][1]);
            if (row0 + 8 < M)
                *(float2*)(C + (size_t)(row0 + 8) * 128 + col) =
                    make_float2(acc[mf][nf][2], acc[mf][nf][3]);
        }
    }
}

// ---------------------------------------------------------------------------
// GEMM2: A = fp16 plane (from prop1), KT=128. All cp.async + LDSM.
// ---------------------------------------------------------------------------
__global__ __launch_bounds__(256, 2) void tgemm_h16(
    const unsigned short* __restrict__ Ah,
    const unsigned short* __restrict__ Bhi, const unsigned short* __restrict__ Blo,
    float* __restrict__ C, int M)
{
    extern __shared__ char sm[];
    const uint32_t smb = smem_u32(sm);
    constexpr int KT = HID;

    const int t = threadIdx.x;
    const int w = t >> 5;
    const int lane = t & 31;
    const int g = lane >> 2;
    const int tg = lane & 3;
    const int warp_m = (w & 3) * 32;
    const int warp_n = (w >> 2) * 64;
    const int blockRow = blockIdx.x * 128;

    const int q = lane >> 3;
    const int s8 = lane & 7;
    uint32_t aLane[2];
#pragma unroll
    for (int mf = 0; mf < 2; mf++)
        aLane[mf] = (uint32_t)(warp_m + mf * 16 + ((q & 1) << 3) + s8) * (LDA * 2) + ((q >> 1)) * 16;
    uint32_t bLane[4];
#pragma unroll
    for (int p = 0; p < 4; p++)
        bLane[p] = (uint32_t)(warp_n + p * 16 + ((q >> 1) << 3) + s8) * (LDA * 2) + (q & 1) * 16;

    const int lr = t >> 1;
    const int ko = (t & 1) * 16;
    int grow = blockRow + lr;
    if (grow > M - 1) grow = M - 1;
    const unsigned short* apH = Ah + (size_t)grow * KT + ko;
    const unsigned short* bpH = Bhi + (size_t)lr * KT + ko;
    const unsigned short* bpL = Blo + (size_t)lr * KT + ko;
    const uint32_t dstb = smb + lr * 80 + ko * 2;

    float acc[2][8][4];
#pragma unroll
    for (int i = 0; i < 2; i++)
#pragma unroll
        for (int j = 0; j < 8; j++)
#pragma unroll
            for (int k = 0; k < 4; k++) acc[i][j][k] = 0.0f;

    constexpr int NCHUNK = KT / 32;

    {
        const uint32_t db = dstb;
        CP16(db,             apH);  CP16(db + 16,             apH + 8);
        CP16(db + 1 * PLANE, bpH);  CP16(db + 1 * PLANE + 16, bpH + 8);
        CP16(db + 2 * PLANE, bpL);  CP16(db + 2 * PLANE + 16, bpL + 8);
        CPC();
    }

    int cur = 0;
#pragma unroll 1
    for (int c = 0; c < NCHUNK; c++) {
        if (c + 1 < NCHUNK) {
            const int kt = (c + 1) * 32;
            const uint32_t db = dstb + (cur ^ 1) * BUF3;
            CP16(db,             apH + kt);  CP16(db + 16,             apH + kt + 8);
            CP16(db + 1 * PLANE, bpH + kt);  CP16(db + 1 * PLANE + 16, bpH + kt + 8);
            CP16(db + 2 * PLANE, bpL + kt);  CP16(db + 2 * PLANE + 16, bpL + kt + 8);
            CPC();
            CPW(1);
        } else {
            CPW(0);
        }
        __syncthreads();

        const uint32_t buf = smb + (uint32_t)cur * BUF3;

#pragma unroll
        for (int ks = 0; ks < 2; ks++) {
            uint32_t ah[2][4];
#pragma unroll
            for (int mf = 0; mf < 2; mf++)
                ldsm4(ah[mf][0], ah[mf][1], ah[mf][2], ah[mf][3],
                      buf + aLane[mf] + ks * 32);
            uint32_t bh[8][2], bl[8][2];
#pragma unroll
            for (int p = 0; p < 4; p++) {
                ldsm4(bh[2 * p][0], bh[2 * p][1], bh[2 * p + 1][0], bh[2 * p + 1][1],
                      buf + 1 * PLANE + bLane[p] + ks * 32);
                ldsm4(bl[2 * p][0], bl[2 * p][1], bl[2 * p + 1][0], bl[2 * p + 1][1],
                      buf + 2 * PLANE + bLane[p] + ks * 32);
            }
#pragma unroll
            for (int nf = 0; nf < 8; nf++) {
                MMA_F16(acc[0][nf][0], acc[0][nf][1], acc[0][nf][2], acc[0][nf][3],
                        ah[0][0], ah[0][1], ah[0][2], ah[0][3], bh[nf][0], bh[nf][1]);
                MMA_F16(acc[1][nf][0], acc[1][nf][1], acc[1][nf][2], acc[1][nf][3],
                        ah[1][0], ah[1][1], ah[1][2], ah[1][3], bh[nf][0], bh[nf][1]);
            }
#pragma unroll
            for (int nf = 0; nf < 8; nf++) {
                MMA_F16(acc[0][nf][0], acc[0][nf][1], acc[0][nf][2], acc[0][nf][3],
                        ah[0][0], ah[0][1], ah[0][2], ah[0][3], bl[nf][0], bl[nf][1]);
                MMA_F16(acc[1][nf][0], acc[1][nf][1], acc[1][nf][2], acc[1][nf][3],
                        ah[1][0], ah[1][1], ah[1][2], ah[1][3], bl[nf][0], bl[nf][1]);
            }
        }
        __syncthreads();
        cur ^= 1;
    }

#pragma unroll
    for (int mf = 0; mf < 2; mf++) {
#pragma unroll
        for (int nf = 0; nf < 8; nf++) {
            const int row0 = blockRow + warp_m + mf * 16 + g;
            const int col = warp_n + nf * 8 + 2 * tg;
            if (row0 < M)
                *(float2*)(C + (size_t)row0 * 128 + col) =
                    make_float2(acc[mf][nf][0], acc[mf][nf][1]);
            if (row0 + 8 < M)
                *(float2*)(C + (size_t)(row0 + 8) * 128 + col) =
                    make_float2(acc[mf][nf][2], acc[mf][nf][3]);
        }
    }
}

// ---------------------------------------------------------------------------
// CSR propagation, 4-way MLP unroll; segments via g_off/g_end
// ---------------------------------------------------------------------------
#define PROP_BODY()                                                              \
    int e = g_off[warp];                                                         \
    const int end = g_end[warp];                                                 \
    for (; e + 4 <= end; e += 4) {                                               \
        int s0 = g_es[e], s1 = g_es[e + 1], s2 = g_es[e + 2], s3 = g_es[e + 3];  \
        float m0 = g_en[e], m1 = g_en[e + 1], m2 = g_en[e + 2], m3 = g_en[e + 3];\
        float4 v0 = ((const float4*)(H + (size_t)s0 * HID))[lane];               \
        float4 v1 = ((const float4*)(H + (size_t)s1 * HID))[lane];               \
        float4 v2 = ((const float4*)(H + (size_t)s2 * HID))[lane];               \
        float4 v3 = ((const float4*)(H + (size_t)s3 * HID))[lane];               \
        ax = fmaf(v0.x, m0, ax); ay = fmaf(v0.y, m0, ay);                        \
        az = fmaf(v0.z, m0, az); aw = fmaf(v0.w, m0, aw);                        \
        ax = fmaf(v1.x, m1, ax); ay = fmaf(v1.y, m1, ay);                        \
        az = fmaf(v1.z, m1, az); aw = fmaf(v1.w, m1, aw);                        \
        ax = fmaf(v2.x, m2, ax); ay = fmaf(v2.y, m2, ay);                        \
        az = fmaf(v2.z, m2, az); aw = fmaf(v2.w, m2, aw);                        \
        ax = fmaf(v3.x, m3, ax); ay = fmaf(v3.y, m3, ay);                        \
        az = fmaf(v3.z, m3, az); aw = fmaf(v3.w, m3, aw);                        \
    }                                                                            \
    for (; e < end; e++) {                                                       \
        int s0 = g_es[e];                                                        \
        float m0 = g_en[e];                                                      \
        float4 v0 = ((const float4*)(H + (size_t)s0 * HID))[lane];               \
        ax = fmaf(v0.x, m0, ax); ay = fmaf(v0.y, m0, ay);                        \
        az = fmaf(v0.z, m0, az); aw = fmaf(v0.w, m0, aw);                        \
    }

__global__ __launch_bounds__(256) void k_prop_csr_split(
    const float* __restrict__ H,
    const float* __restrict__ b)
{
    int warp = (blockIdx.x * blockDim.x + threadIdx.x) >> 5;
    if (warp >= NN) return;
    int lane = threadIdx.x & 31;

    float di = g_dinv[warp];
    float s = di * di;
    float4 bb = ((const float4*)b)[lane];
    float4 v = ((const float4*)(H + (size_t)warp * HID))[lane];
    float ax = fmaf(v.x, s, bb.x);
    float ay = fmaf(v.y, s, bb.y);
    float az = fmaf(v.z, s, bb.z);
    float aw = fmaf(v.w, s, bb.w);

    PROP_BODY()

    ax = fmaxf(ax, 0.f); ay = fmaxf(ay, 0.f);
    az = fmaxf(az, 0.f); aw = fmaxf(aw, 0.f);
    uint32_t w0 = pack_h2(ax, ay);
    uint32_t w1 = pack_h2(az, aw);
    size_t o = (size_t)warp * HID + lane * 4;
    *(uint2*)(g_hh + o) = make_uint2(w0, w1);
}

__global__ __launch_bounds__(256) void k_prop_csr_out(
    const float* __restrict__ H,
    const float* __restrict__ bmu,
    const float* __restrict__ blv,
    float* __restrict__ out)
{
    int warp = (blockIdx.x * blockDim.x + threadIdx.x) >> 5;
    if (warp >= NN) return;
    int lane = threadIdx.x & 31;

    float di = g_dinv[warp];
    float s = di * di;
    float4 bb;
    float* dstp;
    if (lane < 16) {
        bb = ((const float4*)bmu)[lane];
        dstp = out + (size_t)warp * 64 + lane * 4;
    } else {
        bb = ((const float4*)blv)[lane - 16];
        dstp = out + (size_t)NN * 64 + (size_t)warp * 64 + (lane - 16) * 4;
    }
    float4 v = ((const float4*)(H + (size_t)warp * HID))[lane];
    float ax = fmaf(v.x, s, bb.x);
    float ay = fmaf(v.y, s, bb.y);
    float az = fmaf(v.z, s, bb.z);
    float aw = fmaf(v.w, s, bb.w);

    PROP_BODY()

    *(float4*)dstp = make_float4(ax, ay, az, aw);
}

// ---------------------------------------------------------------------------
extern "C" void kernel_launch(void* const* d_in, const int* in_sizes, int n_in,
                              void* d_out, int out_size)
{
    const float* x   = (const float*)d_in[0];
    const int*   ei  = (const int*)d_in[1];
    const float* W1  = (const float*)d_in[2];
    const float* b1  = (const float*)d_in[3];
    const float* Wmu = (const float*)d_in[4];
    const float* bmu = (const float*)d_in[5];
    const float* Wlv = (const float*)d_in[6];
    const float* blv = (const float*)d_in[7];
    float* out = (float*)d_out;

    const int* src = ei;
    const int* dst = ei + NE;

    float *h_ptr;
    cudaGetSymbolAddress((void**)&h_ptr, g_h);
    unsigned short *hh, *w1hi, *w1lo, *w2hi, *w2lo;
    cudaGetSymbolAddress((void**)&hh, g_hh);
    cudaGetSymbolAddress((void**)&w1hi, g_w1hi);
    cudaGetSymbolAddress((void**)&w1lo, g_w1lo);
    cudaGetSymbolAddress((void**)&w2hi, g_w2hi);
    cudaGetSymbolAddress((void**)&w2lo, g_w2lo);

    cudaFuncSetAttribute(tgemm_f32a, cudaFuncAttributeMaxDynamicSharedMemorySize, SMEM_GEMM);
    cudaFuncSetAttribute(tgemm_h16, cudaFuncAttributeMaxDynamicSharedMemorySize, SMEM_GEMM);

    const int TB = 256;

    // Side stream + fork/join events (host-side only; created per call)
    cudaStream_t s2;
    cudaStreamCreateWithFlags(&s2, cudaStreamNonBlocking);
    cudaEvent_t ev_fork, ev_join;
    cudaEventCreateWithFlags(&ev_fork, cudaEventDisableTiming);
    cudaEventCreateWithFlags(&ev_join, cudaEventDisableTiming);

    // --- main stream: W1 conversion (GEMM1 dependency) ---
    k_convw1<<<128, TB>>>(W1);

    // --- fork: CSR build on s2, concurrent with GEMM1 on main ---
    cudaEventRecord(ev_fork, 0);
    cudaStreamWaitEvent(s2, ev_fork, 0);

    k_count_init<<<2564, TB, 0, s2>>>(dst, Wmu, Wlv);
    k_alloc<<<NB, 1024, 0, s2>>>();
    k_scatter<<<(NE + TB - 1) / TB, TB, 0, s2>>>(src, dst);
    cudaEventRecord(ev_join, s2);

    // --- main stream: Layer 1 GEMM ---
    tgemm_f32a<<<(NN + 127) / 128, 256, SMEM_GEMM>>>(x, w1hi, w1lo, h_ptr, NN);

    // --- join: prop1 needs both GEMM1 and CSR ---
    cudaStreamWaitEvent(0, ev_join, 0);

    // --- Propagate + ReLU + fp16 pack ---
    k_prop_csr_split<<<(NN * 32 + TB - 1) / TB, TB>>>(h_ptr, b1);

    // --- Layer 2: h2 = relu(p) @ [W_mu | W_logvar] ---
    tgemm_h16<<<(NN + 127) / 128, 256, SMEM_GEMM>>>(hh, w2hi, w2lo, h_ptr, NN);

    // --- Propagate to split output ---
    k_prop_csr_out<<<(NN * 32 + TB - 1) / TB, TB>>>(h_ptr, bmu, blv, out);
}

// round 16
// speedup vs baseline: 1.5352x; 1.1463x over previous
#include <cuda_runtime.h>
#include <cuda_fp16.h>
#include <cstdint>

#define NN 100000
#define NE 640000
#define INC 256
#define HID 128
#define NB  ((NN + 1023) / 1024)

// ---------------- scratch (__device__ globals) ----------------
__device__ unsigned short g_ha[(size_t)NN * HID];     // fp16: GEMM1 out, later GEMM2 out
__device__ unsigned short g_hb[(size_t)NN * HID];     // fp16: relu(prop1) = GEMM2 A
__device__ unsigned short g_w1hi[INC * HID];          // [n=128][k=256] fp16
__device__ unsigned short g_w1lo[INC * HID];
__device__ unsigned short g_w2hi[HID * HID];          // [n=128][k=128] fp16
__device__ unsigned short g_w2lo[HID * HID];
__device__ float g_dinv[NN];
__device__ int   g_cnt[NN];          // zero on entry; re-zeroed by k_alloc
__device__ int   g_off[NN];
__device__ int   g_end[NN];
__device__ int   g_cursor[NN];
__device__ int   g_es[NE];
__device__ float g_en[NE];
__device__ int   g_total;

__device__ __forceinline__ void split_f16(float x, unsigned short& hi, unsigned short& lo) {
    __half h = __float2half_rn(x);
    float hf = __half2float(h);
    __half l = __float2half_rn(x - hf);
    hi = *reinterpret_cast<unsigned short*>(&h);
    lo = *reinterpret_cast<unsigned short*>(&l);
}

// pack two floats into one f16x2 word: .lo = a, .hi = b
__device__ __forceinline__ uint32_t pack_h2(float a, float b) {
    uint32_t r;
    asm("cvt.rn.f16x2.f32 %0, %1, %2;" : "=r"(r) : "f"(b), "f"(a));
    return r;
}

__device__ __forceinline__ uint32_t smem_u32(const void* p) {
    uint32_t a;
    asm("{ .reg .u64 t; cvta.to.shared.u64 t, %1; cvt.u32.u64 %0, t; }" : "=r"(a) : "l"(p));
    return a;
}

__device__ __forceinline__ void ldsm4(uint32_t& d0, uint32_t& d1, uint32_t& d2, uint32_t& d3,
                                      uint32_t addr) {
    asm volatile("ldmatrix.sync.aligned.m8n8.x4.shared.b16 {%0,%1,%2,%3}, [%4];"
                 : "=r"(d0), "=r"(d1), "=r"(d2), "=r"(d3) : "r"(addr));
}

#define CP16(d, s) asm volatile("cp.async.cg.shared.global [%0], [%1], 16;" :: "r"(d), "l"(s) : "memory")
#define CPC()      asm volatile("cp.async.commit_group;" ::: "memory")
#define CPW(n)     asm volatile("cp.async.wait_group %0;" :: "n"(n) : "memory")

#define MMA_F16(c0,c1,c2,c3,a0,a1,a2,a3,b0,b1)                                   \
    asm volatile("mma.sync.aligned.m16n8k16.row.col.f32.f16.f16.f32 "            \
        "{%0,%1,%2,%3}, {%4,%5,%6,%7}, {%8,%9}, {%0,%1,%2,%3};"                  \
        : "+f"(c0), "+f"(c1), "+f"(c2), "+f"(c3)                                  \
        : "r"(a0), "r"(a1), "r"(a2), "r"(a3), "r"(b0), "r"(b1))

// ---------------------------------------------------------------------------
// W1 conversion (must precede GEMM1, main stream)
// ---------------------------------------------------------------------------
__global__ void k_convw1(const float* __restrict__ W1) {
    int i = blockIdx.x * 256 + threadIdx.x;      // i = n*256 + k, 32768 total
    int n = i >> 8, k = i & 255;
    unsigned short h, l;
    split_f16(W1[k * 128 + n], h, l);
    g_w1hi[i] = h;
    g_w1lo[i] = l;
}

// ---------------------------------------------------------------------------
// Side-stream: degree count (blocks 0..2499) + convW2 (2500..2563) + reset
// ---------------------------------------------------------------------------
__global__ void k_count_init(const int* __restrict__ dst,
                             const float* __restrict__ Wmu,
                             const float* __restrict__ Wlv)
{
    int b = blockIdx.x;
    int t = threadIdx.x;
    if (b == 0 && t == 0) g_total = 0;
    if (b < 2500) {
        int e = b * 256 + t;                 // NE = 2500*256 exactly
        atomicAdd(&g_cnt[dst[e]], 1);
    } else {
        int i = (b - 2500) * 256 + t;        // i = n*128 + k, 16384 total
        int n = i >> 7, k = i & 127;
        float v = (n < 64) ? Wmu[k * 64 + n] : Wlv[k * 64 + (n - 64)];
        unsigned short h, l;
        split_f16(v, h, l);
        g_w2hi[i] = h;
        g_w2lo[i] = l;
    }
}

// ---------------------------------------------------------------------------
// Segment allocation: block-local scan + atomic base grab (+dinv, cnt reset)
// ---------------------------------------------------------------------------
__global__ __launch_bounds__(1024) void k_alloc() {
    __shared__ int sm[1024];
    __shared__ int base;
    const int t = threadIdx.x;
    const int i = blockIdx.x * 1024 + t;
    int v = 0;
    if (i < NN) {
        v = g_cnt[i];
        g_cnt[i] = 0;
        g_dinv[i] = rsqrtf(1.0f + (float)v);
    }
    sm[t] = v;
    __syncthreads();
#pragma unroll
    for (int d = 1; d < 1024; d <<= 1) {
        int x = (t >= d) ? sm[t - d] : 0;
        __syncthreads();
        sm[t] += x;
        __syncthreads();
    }
    if (t == 1023) base = atomicAdd(&g_total, sm[1023]);
    __syncthreads();
    if (i < NN) {
        int off = base + sm[t] - v;
        g_off[i] = off;
        g_end[i] = off + v;
        g_cursor[i] = off;
    }
}

__global__ void k_scatter(const int* __restrict__ src, const int* __restrict__ dst) {
    int e = blockIdx.x * blockDim.x + threadIdx.x;
    if (e >= NE) return;
    int s = src[e], d = dst[e];
    int pos = atomicAdd(&g_cursor[d], 1);
    g_es[pos] = s;
    g_en[pos] = g_dinv[s] * g_dinv[d];
}

// ---------------------------------------------------------------------------
// Shared GEMM geometry: LDA=40 shorts/row (80 B), planes of 128 rows.
// buffer = [A | BHI | BLO], double buffered. 2-pass fp16: a*bh + a*bl.
// C output is fp16 (packed pairs).
// ---------------------------------------------------------------------------
#define LDA   40
#define PLANE 10240
#define BUF3  (3 * PLANE)
#define SMEM_GEMM (2 * BUF3)

// ---------------------------------------------------------------------------
// GEMM1: C[M,128] (fp16) = x @ W^T. A fp32 LDG-prefetched, converted once
// to fp16 plane, STS; inner loop all-LDSM. B (fp16 hi/lo) via cp.async.
// ---------------------------------------------------------------------------
__global__ __launch_bounds__(256, 2) void tgemm_f32a(
    const float* __restrict__ A,
    const unsigned short* __restrict__ Bhi, const unsigned short* __restrict__ Blo,
    unsigned short* __restrict__ C, int M)
{
    extern __shared__ char sm[];
    const uint32_t smb = smem_u32(sm);
    constexpr int KT = INC;   // 256

    const int t = threadIdx.x;
    const int w = t >> 5;
    const int lane = t & 31;
    const int g = lane >> 2;
    const int tg = lane & 3;
    const int warp_m = (w & 3) * 32;
    const int warp_n = (w >> 2) * 64;
    const int blockRow = blockIdx.x * 128;

    const int q = lane >> 3;
    const int s8 = lane & 7;
    uint32_t aLane[2];
#pragma unroll
    for (int mf = 0; mf < 2; mf++)
        aLane[mf] = (uint32_t)(warp_m + mf * 16 + ((q & 1) << 3) + s8) * (LDA * 2) + ((q >> 1)) * 16;
    uint32_t bLane[4];
#pragma unroll
    for (int p = 0; p < 4; p++)
        bLane[p] = (uint32_t)(warp_n + p * 16 + ((q >> 1) << 3) + s8) * (LDA * 2) + (q & 1) * 16;

    const int lr = t >> 1;
    const int ko = (t & 1) * 16;
    int grow = blockRow + lr;
    if (grow > M - 1) grow = M - 1;
    const float* ap = A + (size_t)grow * KT + ko;
    const unsigned short* bpH = Bhi + (size_t)lr * KT + ko;
    const unsigned short* bpL = Blo + (size_t)lr * KT + ko;
    const uint32_t stOff = (uint32_t)lr * 80 + (uint32_t)ko * 2;

    float acc[2][8][4];
#pragma unroll
    for (int i = 0; i < 2; i++)
#pragma unroll
        for (int j = 0; j < 8; j++)
#pragma unroll
            for (int k = 0; k < 4; k++) acc[i][j][k] = 0.0f;

    constexpr int NCHUNK = KT / 32;   // 8

    float4 ra0 = *(const float4*)(ap);
    float4 ra1 = *(const float4*)(ap + 4);
    float4 ra2 = *(const float4*)(ap + 8);
    float4 ra3 = *(const float4*)(ap + 12);
    {
        const uint32_t dB = smb + stOff;
        CP16(dB + 1 * PLANE, bpH);  CP16(dB + 1 * PLANE + 16, bpH + 8);
        CP16(dB + 2 * PLANE, bpL);  CP16(dB + 2 * PLANE + 16, bpL + 8);
        CPC();
    }

    int cur = 0;
#pragma unroll 1
    for (int c = 0; c < NCHUNK; c++) {
        {
            uint32_t p0 = pack_h2(ra0.x, ra0.y);
            uint32_t p1 = pack_h2(ra0.z, ra0.w);
            uint32_t p2 = pack_h2(ra1.x, ra1.y);
            uint32_t p3 = pack_h2(ra1.z, ra1.w);
            uint32_t p4 = pack_h2(ra2.x, ra2.y);
            uint32_t p5 = pack_h2(ra2.z, ra2.w);
            uint32_t p6 = pack_h2(ra3.x, ra3.y);
            uint32_t p7 = pack_h2(ra3.z, ra3.w);
            char* base = sm + (size_t)cur * BUF3 + stOff;
            *(uint4*)(base)      = make_uint4(p0, p1, p2, p3);
            *(uint4*)(base + 16) = make_uint4(p4, p5, p6, p7);
        }
        if (c + 1 < NCHUNK) {
            const int kt = (c + 1) * 32;
            ra0 = *(const float4*)(ap + kt);
            ra1 = *(const float4*)(ap + kt + 4);
            ra2 = *(const float4*)(ap + kt + 8);
            ra3 = *(const float4*)(ap + kt + 12);
            const uint32_t dB = smb + (cur ^ 1) * BUF3 + stOff;
            CP16(dB + 1 * PLANE, bpH + kt);  CP16(dB + 1 * PLANE + 16, bpH + kt + 8);
            CP16(dB + 2 * PLANE, bpL + kt);  CP16(dB + 2 * PLANE + 16, bpL + kt + 8);
            CPC();
            CPW(1);
        } else {
            CPW(0);
        }
        __syncthreads();

        const uint32_t buf = smb + (uint32_t)cur * BUF3;

#pragma unroll
        for (int ks = 0; ks < 2; ks++) {
            uint32_t ah[2][4];
#pragma unroll
            for (int mf = 0; mf < 2; mf++)
                ldsm4(ah[mf][0], ah[mf][1], ah[mf][2], ah[mf][3],
                      buf + aLane[mf] + ks * 32);
            uint32_t bh[8][2], bl[8][2];
#pragma unroll
            for (int p = 0; p < 4; p++) {
                ldsm4(bh[2 * p][0], bh[2 * p][1], bh[2 * p + 1][0], bh[2 * p + 1][1],
                      buf + 1 * PLANE + bLane[p] + ks * 32);
                ldsm4(bl[2 * p][0], bl[2 * p][1], bl[2 * p + 1][0], bl[2 * p + 1][1],
                      buf + 2 * PLANE + bLane[p] + ks * 32);
            }
#pragma unroll
            for (int nf = 0; nf < 8; nf++) {
                MMA_F16(acc[0][nf][0], acc[0][nf][1], acc[0][nf][2], acc[0][nf][3],
                        ah[0][0], ah[0][1], ah[0][2], ah[0][3], bh[nf][0], bh[nf][1]);
                MMA_F16(acc[1][nf][0], acc[1][nf][1], acc[1][nf][2], acc[1][nf][3],
                        ah[1][0], ah[1][1], ah[1][2], ah[1][3], bh[nf][0], bh[nf][1]);
            }
#pragma unroll
            for (int nf = 0; nf < 8; nf++) {
                MMA_F16(acc[0][nf][0], acc[0][nf][1], acc[0][nf][2], acc[0][nf][3],
                        ah[0][0], ah[0][1], ah[0][2], ah[0][3], bl[nf][0], bl[nf][1]);
                MMA_F16(acc[1][nf][0], acc[1][nf][1], acc[1][nf][2], acc[1][nf][3],
                        ah[1][0], ah[1][1], ah[1][2], ah[1][3], bl[nf][0], bl[nf][1]);
            }
        }
        __syncthreads();
        cur ^= 1;
    }

    // epilogue: pack fp32 acc pairs -> fp16, store 4 B per pair
#pragma unroll
    for (int mf = 0; mf < 2; mf++) {
#pragma unroll
        for (int nf = 0; nf < 8; nf++) {
            const int row0 = blockRow + warp_m + mf * 16 + g;
            const int col = warp_n + nf * 8 + 2 * tg;
            if (row0 < M)
                *(uint32_t*)(C + (size_t)row0 * 128 + col) =
                    pack_h2(acc[mf][nf][0], acc[mf][nf][1]);
            if (row0 + 8 < M)
                *(uint32_t*)(C + (size_t)(row0 + 8) * 128 + col) =
                    pack_h2(acc[mf][nf][2], acc[mf][nf][3]);
        }
    }
}

// ---------------------------------------------------------------------------
// GEMM2: A = fp16 plane (from prop1), KT=128. All cp.async + LDSM. fp16 out.
// ---------------------------------------------------------------------------
__global__ __launch_bounds__(256, 2) void tgemm_h16(
    const unsigned short* __restrict__ Ah,
    const unsigned short* __restrict__ Bhi, const unsigned short* __restrict__ Blo,
    unsigned short* __restrict__ C, int M)
{
    extern __shared__ char sm[];
    const uint32_t smb = smem_u32(sm);
    constexpr int KT = HID;

    const int t = threadIdx.x;
    const int w = t >> 5;
    const int lane = t & 31;
    const int g = lane >> 2;
    const int tg = lane & 3;
    const int warp_m = (w & 3) * 32;
    const int warp_n = (w >> 2) * 64;
    const int blockRow = blockIdx.x * 128;

    const int q = lane >> 3;
    const int s8 = lane & 7;
    uint32_t aLane[2];
#pragma unroll
    for (int mf = 0; mf < 2; mf++)
        aLane[mf] = (uint32_t)(warp_m + mf * 16 + ((q & 1) << 3) + s8) * (LDA * 2) + ((q >> 1)) * 16;
    uint32_t bLane[4];
#pragma unroll
    for (int p = 0; p < 4; p++)
        bLane[p] = (uint32_t)(warp_n + p * 16 + ((q >> 1) << 3) + s8) * (LDA * 2) + (q & 1) * 16;

    const int lr = t >> 1;
    const int ko = (t & 1) * 16;
    int grow = blockRow + lr;
    if (grow > M - 1) grow = M - 1;
    const unsigned short* apH = Ah + (size_t)grow * KT + ko;
    const unsigned short* bpH = Bhi + (size_t)lr * KT + ko;
    const unsigned short* bpL = Blo + (size_t)lr * KT + ko;
    const uint32_t dstb = smb + lr * 80 + ko * 2;

    float acc[2][8][4];
#pragma unroll
    for (int i = 0; i < 2; i++)
#pragma unroll
        for (int j = 0; j < 8; j++)
#pragma unroll
            for (int k = 0; k < 4; k++) acc[i][j][k] = 0.0f;

    constexpr int NCHUNK = KT / 32;

    {
        const uint32_t db = dstb;
        CP16(db,             apH);  CP16(db + 16,             apH + 8);
        CP16(db + 1 * PLANE, bpH);  CP16(db + 1 * PLANE + 16, bpH + 8);
        CP16(db + 2 * PLANE, bpL);  CP16(db + 2 * PLANE + 16, bpL + 8);
        CPC();
    }

    int cur = 0;
#pragma unroll 1
    for (int c = 0; c < NCHUNK; c++) {
        if (c + 1 < NCHUNK) {
            const int kt = (c + 1) * 32;
            const uint32_t db = dstb + (cur ^ 1) * BUF3;
            CP16(db,             apH + kt);  CP16(db + 16,             apH + kt + 8);
            CP16(db + 1 * PLANE, bpH + kt);  CP16(db + 1 * PLANE + 16, bpH + kt + 8);
            CP16(db + 2 * PLANE, bpL + kt);  CP16(db + 2 * PLANE + 16, bpL + kt + 8);
            CPC();
            CPW(1);
        } else {
            CPW(0);
        }
        __syncthreads();

        const uint32_t buf = smb + (uint32_t)cur * BUF3;

#pragma unroll
        for (int ks = 0; ks < 2; ks++) {
            uint32_t ah[2][4];
#pragma unroll
            for (int mf = 0; mf < 2; mf++)
                ldsm4(ah[mf][0], ah[mf][1], ah[mf][2], ah[mf][3],
                      buf + aLane[mf] + ks * 32);
            uint32_t bh[8][2], bl[8][2];
#pragma unroll
            for (int p = 0; p < 4; p++) {
                ldsm4(bh[2 * p][0], bh[2 * p][1], bh[2 * p + 1][0], bh[2 * p + 1][1],
                      buf + 1 * PLANE + bLane[p] + ks * 32);
                ldsm4(bl[2 * p][0], bl[2 * p][1], bl[2 * p + 1][0], bl[2 * p + 1][1],
                      buf + 2 * PLANE + bLane[p] + ks * 32);
            }
#pragma unroll
            for (int nf = 0; nf < 8; nf++) {
                MMA_F16(acc[0][nf][0], acc[0][nf][1], acc[0][nf][2], acc[0][nf][3],
                        ah[0][0], ah[0][1], ah[0][2], ah[0][3], bh[nf][0], bh[nf][1]);
                MMA_F16(acc[1][nf][0], acc[1][nf][1], acc[1][nf][2], acc[1][nf][3],
                        ah[1][0], ah[1][1], ah[1][2], ah[1][3], bh[nf][0], bh[nf][1]);
            }
#pragma unroll
            for (int nf = 0; nf < 8; nf++) {
                MMA_F16(acc[0][nf][0], acc[0][nf][1], acc[0][nf][2], acc[0][nf][3],
                        ah[0][0], ah[0][1], ah[0][2], ah[0][3], bl[nf][0], bl[nf][1]);
                MMA_F16(acc[1][nf][0], acc[1][nf][1], acc[1][nf][2], acc[1][nf][3],
                        ah[1][0], ah[1][1], ah[1][2], ah[1][3], bl[nf][0], bl[nf][1]);
            }
        }
        __syncthreads();
        cur ^= 1;
    }

#pragma unroll
    for (int mf = 0; mf < 2; mf++) {
#pragma unroll
        for (int nf = 0; nf < 8; nf++) {
            const int row0 = blockRow + warp_m + mf * 16 + g;
            const int col = warp_n + nf * 8 + 2 * tg;
            if (row0 < M)
                *(uint32_t*)(C + (size_t)row0 * 128 + col) =
                    pack_h2(acc[mf][nf][0], acc[mf][nf][1]);
            if (row0 + 8 < M)
                *(uint32_t*)(C + (size_t)(row0 + 8) * 128 + col) =
                    pack_h2(acc[mf][nf][2], acc[mf][nf][3]);
        }
    }
}

// ---------------------------------------------------------------------------
// CSR propagation on fp16 features: lane owns 4 channels (uint2 = 4 halves).
// Accumulates in fp32. 4-way MLP unroll.
// ---------------------------------------------------------------------------
__device__ __forceinline__ float2 h2f(uint32_t u) {
    __half2 h = *reinterpret_cast<__half2*>(&u);
    return __half22float2(h);
}

#define PROP_BODY_H16()                                                          \
    int e = g_off[warp];                                                         \
    const int end = g_end[warp];                                                 \
    for (; e + 4 <= end; e += 4) {                                               \
        int s0 = g_es[e], s1 = g_es[e + 1], s2 = g_es[e + 2], s3 = g_es[e + 3];  \
        float m0 = g_en[e], m1 = g_en[e + 1], m2 = g_en[e + 2], m3 = g_en[e + 3];\
        uint2 u0 = ((const uint2*)(H + (size_t)s0 * HID))[lane];                 \
        uint2 u1 = ((const uint2*)(H + (size_t)s1 * HID))[lane];                 \
        uint2 u2 = ((const uint2*)(H + (size_t)s2 * HID))[lane];                 \
        uint2 u3 = ((const uint2*)(H + (size_t)s3 * HID))[lane];                 \
        float2 a0 = h2f(u0.x), b0 = h2f(u0.y);                                   \
        float2 a1 = h2f(u1.x), b1 = h2f(u1.y);                                   \
        float2 a2 = h2f(u2.x), b2 = h2f(u2.y);                                   \
        float2 a3 = h2f(u3.x), b3 = h2f(u3.y);                                   \
        ax = fmaf(a0.x, m0, ax); ay = fmaf(a0.y, m0, ay);                        \
        az = fmaf(b0.x, m0, az); aw = fmaf(b0.y, m0, aw);                        \
        ax = fmaf(a1.x, m1, ax); ay = fmaf(a1.y, m1, ay);                        \
        az = fmaf(b1.x, m1, az); aw = fmaf(b1.y, m1, aw);                        \
        ax = fmaf(a2.x, m2, ax); ay = fmaf(a2.y, m2, ay);                        \
        az = fmaf(b2.x, m2, az); aw = fmaf(b2.y, m2, aw);                        \
        ax = fmaf(a3.x, m3, ax); ay = fmaf(a3.y, m3, ay);                        \
        az = fmaf(b3.x, m3, az); aw = fmaf(b3.y, m3, aw);                        \
    }                                                                            \
    for (; e < end; e++) {                                                       \
        int s0 = g_es[e];                                                        \
        float m0 = g_en[e];                                                      \
        uint2 u0 = ((const uint2*)(H + (size_t)s0 * HID))[lane];                 \
        float2 a0 = h2f(u0.x), b0 = h2f(u0.y);                                   \
        ax = fmaf(a0.x, m0, ax); ay = fmaf(a0.y, m0, ay);                        \
        az = fmaf(b0.x, m0, az); aw = fmaf(b0.y, m0, aw);                        \
    }

__global__ __launch_bounds__(256) void k_prop_csr_split(
    const unsigned short* __restrict__ H,
    const float* __restrict__ b)
{
    int warp = (blockIdx.x * blockDim.x + threadIdx.x) >> 5;
    if (warp >= NN) return;
    int lane = threadIdx.x & 31;

    float di = g_dinv[warp];
    float s = di * di;
    float4 bb = ((const float4*)b)[lane];
    uint2 uv = ((const uint2*)(H + (size_t)warp * HID))[lane];
    float2 v0 = h2f(uv.x), v1 = h2f(uv.y);
    float ax = fmaf(v0.x, s, bb.x);
    float ay = fmaf(v0.y, s, bb.y);
    float az = fmaf(v1.x, s, bb.z);
    float aw = fmaf(v1.y, s, bb.w);

    PROP_BODY_H16()

    ax = fmaxf(ax, 0.f); ay = fmaxf(ay, 0.f);
    az = fmaxf(az, 0.f); aw = fmaxf(aw, 0.f);
    uint32_t w0 = pack_h2(ax, ay);
    uint32_t w1 = pack_h2(az, aw);
    size_t o = (size_t)warp * HID + lane * 4;
    *(uint2*)(g_hb + o) = make_uint2(w0, w1);
}

__global__ __launch_bounds__(256) void k_prop_csr_out(
    const unsigned short* __restrict__ H,
    const float* __restrict__ bmu,
    const float* __restrict__ blv,
    float* __restrict__ out)
{
    int warp = (blockIdx.x * blockDim.x + threadIdx.x) >> 5;
    if (warp >= NN) return;
    int lane = threadIdx.x & 31;

    float di = g_dinv[warp];
    float s = di * di;
    float4 bb;
    float* dstp;
    if (lane < 16) {
        bb = ((const float4*)bmu)[lane];
        dstp = out + (size_t)warp * 64 + lane * 4;
    } else {
        bb = ((const float4*)blv)[lane - 16];
        dstp = out + (size_t)NN * 64 + (size_t)warp * 64 + (lane - 16) * 4;
    }
    uint2 uv = ((const uint2*)(H + (size_t)warp * HID))[lane];
    float2 v0 = h2f(uv.x), v1 = h2f(uv.y);
    float ax = fmaf(v0.x, s, bb.x);
    float ay = fmaf(v0.y, s, bb.y);
    float az = fmaf(v1.x, s, bb.z);
    float aw = fmaf(v1.y, s, bb.w);

    PROP_BODY_H16()

    *(float4*)dstp = make_float4(ax, ay, az, aw);
}

// ---------------------------------------------------------------------------
extern "C" void kernel_launch(void* const* d_in, const int* in_sizes, int n_in,
                              void* d_out, int out_size)
{
    const float* x   = (const float*)d_in[0];
    const int*   ei  = (const int*)d_in[1];
    const float* W1  = (const float*)d_in[2];
    const float* b1  = (const float*)d_in[3];
    const float* Wmu = (const float*)d_in[4];
    const float* bmu = (const float*)d_in[5];
    const float* Wlv = (const float*)d_in[6];
    const float* blv = (const float*)d_in[7];
    float* out = (float*)d_out;

    const int* src = ei;
    const int* dst = ei + NE;

    unsigned short *ha, *hb, *w1hi, *w1lo, *w2hi, *w2lo;
    cudaGetSymbolAddress((void**)&ha, g_ha);
    cudaGetSymbolAddress((void**)&hb, g_hb);
    cudaGetSymbolAddress((void**)&w1hi, g_w1hi);
    cudaGetSymbolAddress((void**)&w1lo, g_w1lo);
    cudaGetSymbolAddress((void**)&w2hi, g_w2hi);
    cudaGetSymbolAddress((void**)&w2lo, g_w2lo);

    cudaFuncSetAttribute(tgemm_f32a, cudaFuncAttributeMaxDynamicSharedMemorySize, SMEM_GEMM);
    cudaFuncSetAttribute(tgemm_h16, cudaFuncAttributeMaxDynamicSharedMemorySize, SMEM_GEMM);

    const int TB = 256;

    // Side stream + fork/join events (host-side only; created per call)
    cudaStream_t s2;
    cudaStreamCreateWithFlags(&s2, cudaStreamNonBlocking);
    cudaEvent_t ev_fork, ev_join;
    cudaEventCreateWithFlags(&ev_fork, cudaEventDisableTiming);
    cudaEventCreateWithFlags(&ev_join, cudaEventDisableTiming);

    // --- main stream: W1 conversion (GEMM1 dependency) ---
    k_convw1<<<128, TB>>>(W1);

    // --- fork: CSR build on s2, concurrent with GEMM1 on main ---
    cudaEventRecord(ev_fork, 0);
    cudaStreamWaitEvent(s2, ev_fork, 0);

    k_count_init<<<2564, TB, 0, s2>>>(dst, Wmu, Wlv);
    k_alloc<<<NB, 1024, 0, s2>>>();
    k_scatter<<<(NE + TB - 1) / TB, TB, 0, s2>>>(src, dst);
    cudaEventRecord(ev_join, s2);

    // --- main stream: Layer 1 GEMM -> fp16 g_ha ---
    tgemm_f32a<<<(NN + 127) / 128, 256, SMEM_GEMM>>>(x, w1hi, w1lo, ha, NN);

    // --- join: prop1 needs both GEMM1 and CSR ---
    cudaStreamWaitEvent(0, ev_join, 0);

    // --- Propagate + ReLU + fp16 pack: g_ha -> g_hb ---
    k_prop_csr_split<<<(NN * 32 + TB - 1) / TB, TB>>>(ha, b1);

    // --- Layer 2: g_hb @ [W_mu | W_logvar] -> fp16 g_ha ---
    tgemm_h16<<<(NN + 127) / 128, 256, SMEM_GEMM>>>(hb, w2hi, w2lo, ha, NN);

    // --- Propagate to split fp32 output: g_ha -> out ---
    k_prop_csr_out<<<(NN * 32 + TB - 1) / TB, TB>>>(ha, bmu, blv, out);
}

// round 17
// speedup vs baseline: 1.8025x; 1.1741x over previous
#include <cuda_runtime.h>
#include <cuda_fp16.h>
#include <cstdint>

#define NN 100000
#define NE 640000
#define INC 256
#define HID 128
#define NB  ((NN + 1023) / 1024)

// ---------------- scratch (__device__ globals) ----------------
__device__ unsigned short g_ha[(size_t)NN * HID];     // fp16: GEMM1 out, later GEMM2 out
__device__ unsigned short g_hb[(size_t)NN * HID];     // fp16: relu(prop1) = GEMM2 A
__device__ unsigned short g_w1[INC * HID];            // [n=128][k=256] fp16
__device__ unsigned short g_w2[HID * HID];            // [n=128][k=128] fp16
__device__ float g_dinv[NN];
__device__ int   g_cnt[NN];          // zero on entry; re-zeroed by k_alloc
__device__ int   g_off[NN];
__device__ int   g_end[NN];
__device__ int   g_cursor[NN];
__device__ uint2 g_ee[NE];           // {src, norm bits} per edge, dst-grouped
__device__ int   g_total;

// pack two floats into one f16x2 word: .lo = a, .hi = b
__device__ __forceinline__ uint32_t pack_h2(float a, float b) {
    uint32_t r;
    asm("cvt.rn.f16x2.f32 %0, %1, %2;" : "=r"(r) : "f"(b), "f"(a));
    return r;
}

__device__ __forceinline__ unsigned short f2h(float x) {
    __half h = __float2half_rn(x);
    return *reinterpret_cast<unsigned short*>(&h);
}

__device__ __forceinline__ uint32_t smem_u32(const void* p) {
    uint32_t a;
    asm("{ .reg .u64 t; cvta.to.shared.u64 t, %1; cvt.u32.u64 %0, t; }" : "=r"(a) : "l"(p));
    return a;
}

__device__ __forceinline__ void ldsm4(uint32_t& d0, uint32_t& d1, uint32_t& d2, uint32_t& d3,
                                      uint32_t addr) {
    asm volatile("ldmatrix.sync.aligned.m8n8.x4.shared.b16 {%0,%1,%2,%3}, [%4];"
                 : "=r"(d0), "=r"(d1), "=r"(d2), "=r"(d3) : "r"(addr));
}

#define CP16(d, s) asm volatile("cp.async.cg.shared.global [%0], [%1], 16;" :: "r"(d), "l"(s) : "memory")
#define CPC()      asm volatile("cp.async.commit_group;" ::: "memory")
#define CPW(n)     asm volatile("cp.async.wait_group %0;" :: "n"(n) : "memory")

#define MMA_F16(c0,c1,c2,c3,a0,a1,a2,a3,b0,b1)                                   \
    asm volatile("mma.sync.aligned.m16n8k16.row.col.f32.f16.f16.f32 "            \
        "{%0,%1,%2,%3}, {%4,%5,%6,%7}, {%8,%9}, {%0,%1,%2,%3};"                  \
        : "+f"(c0), "+f"(c1), "+f"(c2), "+f"(c3)                                  \
        : "r"(a0), "r"(a1), "r"(a2), "r"(a3), "r"(b0), "r"(b1))

// ---------------------------------------------------------------------------
// W1 conversion (must precede GEMM1, main stream)
// ---------------------------------------------------------------------------
__global__ void k_convw1(const float* __restrict__ W1) {
    int i = blockIdx.x * 256 + threadIdx.x;      // i = n*256 + k, 32768 total
    int n = i >> 8, k = i & 255;
    g_w1[i] = f2h(W1[k * 128 + n]);
}

// ---------------------------------------------------------------------------
// Side-stream: degree count (blocks 0..2499) + convW2 (2500..2563) + reset
// ---------------------------------------------------------------------------
__global__ void k_count_init(const int* __restrict__ dst,
                             const float* __restrict__ Wmu,
                             const float* __restrict__ Wlv)
{
    int b = blockIdx.x;
    int t = threadIdx.x;
    if (b == 0 && t == 0) g_total = 0;
    if (b < 2500) {
        int e = b * 256 + t;                 // NE = 2500*256 exactly
        atomicAdd(&g_cnt[dst[e]], 1);
    } else {
        int i = (b - 2500) * 256 + t;        // i = n*128 + k, 16384 total
        int n = i >> 7, k = i & 127;
        float v = (n < 64) ? Wmu[k * 64 + n] : Wlv[k * 64 + (n - 64)];
        g_w2[i] = f2h(v);
    }
}

// ---------------------------------------------------------------------------
// Segment allocation: block-local scan + atomic base grab (+dinv, cnt reset)
// ---------------------------------------------------------------------------
__global__ __launch_bounds__(1024) void k_alloc() {
    __shared__ int sm[1024];
    __shared__ int base;
    const int t = threadIdx.x;
    const int i = blockIdx.x * 1024 + t;
    int v = 0;
    if (i < NN) {
        v = g_cnt[i];
        g_cnt[i] = 0;
        g_dinv[i] = rsqrtf(1.0f + (float)v);
    }
    sm[t] = v;
    __syncthreads();
#pragma unroll
    for (int d = 1; d < 1024; d <<= 1) {
        int x = (t >= d) ? sm[t - d] : 0;
        __syncthreads();
        sm[t] += x;
        __syncthreads();
    }
    if (t == 1023) base = atomicAdd(&g_total, sm[1023]);
    __syncthreads();
    if (i < NN) {
        int off = base + sm[t] - v;
        g_off[i] = off;
        g_end[i] = off + v;
        g_cursor[i] = off;
    }
}

__global__ void k_scatter(const int* __restrict__ src, const int* __restrict__ dst) {
    int e = blockIdx.x * blockDim.x + threadIdx.x;
    if (e >= NE) return;
    int s = src[e], d = dst[e];
    int pos = atomicAdd(&g_cursor[d], 1);
    float nm = g_dinv[s] * g_dinv[d];
    g_ee[pos] = make_uint2((uint32_t)s, __float_as_uint(nm));
}

// ---------------------------------------------------------------------------
// GEMM geometry: LDA=40 shorts/row (80 B), planes of 128 rows.
// buffer = [A | B], double buffered. Single-pass fp16 MMA.
// ---------------------------------------------------------------------------
#define LDA   40
#define PLANE 10240
#define BUF2  (2 * PLANE)
#define SMEM_GEMM (2 * BUF2)

// ---------------------------------------------------------------------------
// GEMM1: C[M,128] (fp16) = x @ W^T. A fp32 LDG-prefetched, converted once
// to fp16 plane, STS; inner loop all-LDSM. B (fp16) via cp.async.
// ---------------------------------------------------------------------------
__global__ __launch_bounds__(256, 2) void tgemm_f32a(
    const float* __restrict__ A,
    const unsigned short* __restrict__ B,
    unsigned short* __restrict__ C, int M)
{
    extern __shared__ char sm[];
    const uint32_t smb = smem_u32(sm);
    constexpr int KT = INC;   // 256

    const int t = threadIdx.x;
    const int w = t >> 5;
    const int lane = t & 31;
    const int g = lane >> 2;
    const int tg = lane & 3;
    const int warp_m = (w & 3) * 32;
    const int warp_n = (w >> 2) * 64;
    const int blockRow = blockIdx.x * 128;

    const int q = lane >> 3;
    const int s8 = lane & 7;
    uint32_t aLane[2];
#pragma unroll
    for (int mf = 0; mf < 2; mf++)
        aLane[mf] = (uint32_t)(warp_m + mf * 16 + ((q & 1) << 3) + s8) * (LDA * 2) + ((q >> 1)) * 16;
    uint32_t bLane[4];
#pragma unroll
    for (int p = 0; p < 4; p++)
        bLane[p] = (uint32_t)(warp_n + p * 16 + ((q >> 1) << 3) + s8) * (LDA * 2) + (q & 1) * 16;

    const int lr = t >> 1;
    const int ko = (t & 1) * 16;
    int grow = blockRow + lr;
    if (grow > M - 1) grow = M - 1;
    const float* ap = A + (size_t)grow * KT + ko;
    const unsigned short* bp = B + (size_t)lr * KT + ko;
    const uint32_t stOff = (uint32_t)lr * 80 + (uint32_t)ko * 2;

    float acc[2][8][4];
#pragma unroll
    for (int i = 0; i < 2; i++)
#pragma unroll
        for (int j = 0; j < 8; j++)
#pragma unroll
            for (int k = 0; k < 4; k++) acc[i][j][k] = 0.0f;

    constexpr int NCHUNK = KT / 32;   // 8

    float4 ra0 = *(const float4*)(ap);
    float4 ra1 = *(const float4*)(ap + 4);
    float4 ra2 = *(const float4*)(ap + 8);
    float4 ra3 = *(const float4*)(ap + 12);
    {
        const uint32_t dB = smb + stOff + PLANE;
        CP16(dB, bp);  CP16(dB + 16, bp + 8);
        CPC();
    }

    int cur = 0;
#pragma unroll 1
    for (int c = 0; c < NCHUNK; c++) {
        {
            uint32_t p0 = pack_h2(ra0.x, ra0.y);
            uint32_t p1 = pack_h2(ra0.z, ra0.w);
            uint32_t p2 = pack_h2(ra1.x, ra1.y);
            uint32_t p3 = pack_h2(ra1.z, ra1.w);
            uint32_t p4 = pack_h2(ra2.x, ra2.y);
            uint32_t p5 = pack_h2(ra2.z, ra2.w);
            uint32_t p6 = pack_h2(ra3.x, ra3.y);
            uint32_t p7 = pack_h2(ra3.z, ra3.w);
            char* base = sm + (size_t)cur * BUF2 + stOff;
            *(uint4*)(base)      = make_uint4(p0, p1, p2, p3);
            *(uint4*)(base + 16) = make_uint4(p4, p5, p6, p7);
        }
        if (c + 1 < NCHUNK) {
            const int kt = (c + 1) * 32;
            ra0 = *(const float4*)(ap + kt);
            ra1 = *(const float4*)(ap + kt + 4);
            ra2 = *(const float4*)(ap + kt + 8);
            ra3 = *(const float4*)(ap + kt + 12);
            const uint32_t dB = smb + (cur ^ 1) * BUF2 + stOff + PLANE;
            CP16(dB, bp + kt);  CP16(dB + 16, bp + kt + 8);
            CPC();
            CPW(1);
        } else {
            CPW(0);
        }
        __syncthreads();

        const uint32_t buf = smb + (uint32_t)cur * BUF2;

#pragma unroll
        for (int ks = 0; ks < 2; ks++) {
            uint32_t ah[2][4];
#pragma unroll
            for (int mf = 0; mf < 2; mf++)
                ldsm4(ah[mf][0], ah[mf][1], ah[mf][2], ah[mf][3],
                      buf + aLane[mf] + ks * 32);
            uint32_t bf[8][2];
#pragma unroll
            for (int p = 0; p < 4; p++)
                ldsm4(bf[2 * p][0], bf[2 * p][1], bf[2 * p + 1][0], bf[2 * p + 1][1],
                      buf + PLANE + bLane[p] + ks * 32);
#pragma unroll
            for (int nf = 0; nf < 8; nf++) {
                MMA_F16(acc[0][nf][0], acc[0][nf][1], acc[0][nf][2], acc[0][nf][3],
                        ah[0][0], ah[0][1], ah[0][2], ah[0][3], bf[nf][0], bf[nf][1]);
                MMA_F16(acc[1][nf][0], acc[1][nf][1], acc[1][nf][2], acc[1][nf][3],
                        ah[1][0], ah[1][1], ah[1][2], ah[1][3], bf[nf][0], bf[nf][1]);
            }
        }
        __syncthreads();
        cur ^= 1;
    }

#pragma unroll
    for (int mf = 0; mf < 2; mf++) {
#pragma unroll
        for (int nf = 0; nf < 8; nf++) {
            const int row0 = blockRow + warp_m + mf * 16 + g;
            const int col = warp_n + nf * 8 + 2 * tg;
            if (row0 < M)
                *(uint32_t*)(C + (size_t)row0 * 128 + col) =
                    pack_h2(acc[mf][nf][0], acc[mf][nf][1]);
            if (row0 + 8 < M)
                *(uint32_t*)(C + (size_t)(row0 + 8) * 128 + col) =
                    pack_h2(acc[mf][nf][2], acc[mf][nf][3]);
        }
    }
}

// ---------------------------------------------------------------------------
// GEMM2: A = fp16 plane (from prop1), KT=128. All cp.async + LDSM. fp16 out.
// ---------------------------------------------------------------------------
__global__ __launch_bounds__(256, 2) void tgemm_h16(
    const unsigned short* __restrict__ Ah,
    const unsigned short* __restrict__ B,
    unsigned short* __restrict__ C, int M)
{
    extern __shared__ char sm[];
    const uint32_t smb = smem_u32(sm);
    constexpr int KT = HID;

    const int t = threadIdx.x;
    const int w = t >> 5;
    const int lane = t & 31;
    const int g = lane >> 2;
    const int tg = lane & 3;
    const int warp_m = (w & 3) * 32;
    const int warp_n = (w >> 2) * 64;
    const int blockRow = blockIdx.x * 128;

    const int q = lane >> 3;
    const int s8 = lane & 7;
    uint32_t aLane[2];
#pragma unroll
    for (int mf = 0; mf < 2; mf++)
        aLane[mf] = (uint32_t)(warp_m + mf * 16 + ((q & 1) << 3) + s8) * (LDA * 2) + ((q >> 1)) * 16;
    uint32_t bLane[4];
#pragma unroll
    for (int p = 0; p < 4; p++)
        bLane[p] = (uint32_t)(warp_n + p * 16 + ((q >> 1) << 3) + s8) * (LDA * 2) + (q & 1) * 16;

    const int lr = t >> 1;
    const int ko = (t & 1) * 16;
    int grow = blockRow + lr;
    if (grow > M - 1) grow = M - 1;
    const unsigned short* apH = Ah + (size_t)grow * KT + ko;
    const unsigned short* bp = B + (size_t)lr * KT + ko;
    const uint32_t dstb = smb + lr * 80 + ko * 2;

    float acc[2][8][4];
#pragma unroll
    for (int i = 0; i < 2; i++)
#pragma unroll
        for (int j = 0; j < 8; j++)
#pragma unroll
            for (int k = 0; k < 4; k++) acc[i][j][k] = 0.0f;

    constexpr int NCHUNK = KT / 32;

    {
        const uint32_t db = dstb;
        CP16(db,         apH);  CP16(db + 16,         apH + 8);
        CP16(db + PLANE, bp);   CP16(db + PLANE + 16, bp + 8);
        CPC();
    }

    int cur = 0;
#pragma unroll 1
    for (int c = 0; c < NCHUNK; c++) {
        if (c + 1 < NCHUNK) {
            const int kt = (c + 1) * 32;
            const uint32_t db = dstb + (cur ^ 1) * BUF2;
            CP16(db,         apH + kt);  CP16(db + 16,         apH + kt + 8);
            CP16(db + PLANE, bp + kt);   CP16(db + PLANE + 16, bp + kt + 8);
            CPC();
            CPW(1);
        } else {
            CPW(0);
        }
        __syncthreads();

        const uint32_t buf = smb + (uint32_t)cur * BUF2;

#pragma unroll
        for (int ks = 0; ks < 2; ks++) {
            uint32_t ah[2][4];
#pragma unroll
            for (int mf = 0; mf < 2; mf++)
                ldsm4(ah[mf][0], ah[mf][1], ah[mf][2], ah[mf][3],
                      buf + aLane[mf] + ks * 32);
            uint32_t bf[8][2];
#pragma unroll
            for (int p = 0; p < 4; p++)
                ldsm4(bf[2 * p][0], bf[2 * p][1], bf[2 * p + 1][0], bf[2 * p + 1][1],
                      buf + PLANE + bLane[p] + ks * 32);
#pragma unroll
            for (int nf = 0; nf < 8; nf++) {
                MMA_F16(acc[0][nf][0], acc[0][nf][1], acc[0][nf][2], acc[0][nf][3],
                        ah[0][0], ah[0][1], ah[0][2], ah[0][3], bf[nf][0], bf[nf][1]);
                MMA_F16(acc[1][nf][0], acc[1][nf][1], acc[1][nf][2], acc[1][nf][3],
                        ah[1][0], ah[1][1], ah[1][2], ah[1][3], bf[nf][0], bf[nf][1]);
            }
        }
        __syncthreads();
        cur ^= 1;
    }

#pragma unroll
    for (int mf = 0; mf < 2; mf++) {
#pragma unroll
        for (int nf = 0; nf < 8; nf++) {
            const int row0 = blockRow + warp_m + mf * 16 + g;
            const int col = warp_n + nf * 8 + 2 * tg;
            if (row0 < M)
                *(uint32_t*)(C + (size_t)row0 * 128 + col) =
                    pack_h2(acc[mf][nf][0], acc[mf][nf][1]);
            if (row0 + 8 < M)
                *(uint32_t*)(C + (size_t)(row0 + 8) * 128 + col) =
                    pack_h2(acc[mf][nf][2], acc[mf][nf][3]);
        }
    }
}

// ---------------------------------------------------------------------------
// CSR propagation on fp16 features: lane owns 4 channels (uint2 = 4 halves).
// Edge data in g_ee (uint2 {src, normbits}). Accum fp32, 4-way MLP unroll.
// ---------------------------------------------------------------------------
__device__ __forceinline__ float2 h2f(uint32_t u) {
    __half2 h = *reinterpret_cast<__half2*>(&u);
    return __half22float2(h);
}

#define PROP_BODY_H16()                                                          \
    int e = g_off[warp];                                                         \
    const int end = g_end[warp];                                                 \
    for (; e + 4 <= end; e += 4) {                                               \
        uint2 e0 = g_ee[e], e1 = g_ee[e + 1], e2 = g_ee[e + 2], e3 = g_ee[e + 3];\
        uint2 u0 = ((const uint2*)(H + (size_t)e0.x * HID))[lane];               \
        uint2 u1 = ((const uint2*)(H + (size_t)e1.x * HID))[lane];               \
        uint2 u2 = ((const uint2*)(H + (size_t)e2.x * HID))[lane];               \
        uint2 u3 = ((const uint2*)(H + (size_t)e3.x * HID))[lane];               \
        float m0 = __uint_as_float(e0.y), m1 = __uint_as_float(e1.y);            \
        float m2 = __uint_as_float(e2.y), m3 = __uint_as_float(e3.y);            \
        float2 a0 = h2f(u0.x), b0 = h2f(u0.y);                                   \
        float2 a1 = h2f(u1.x), b1 = h2f(u1.y);                                   \
        float2 a2 = h2f(u2.x), b2 = h2f(u2.y);                                   \
        float2 a3 = h2f(u3.x), b3 = h2f(u3.y);                                   \
        ax = fmaf(a0.x, m0, ax); ay = fmaf(a0.y, m0, ay);                        \
        az = fmaf(b0.x, m0, az); aw = fmaf(b0.y, m0, aw);                        \
        ax = fmaf(a1.x, m1, ax); ay = fmaf(a1.y, m1, ay);                        \
        az = fmaf(b1.x, m1, az); aw = fmaf(b1.y, m1, aw);                        \
        ax = fmaf(a2.x, m2, ax); ay = fmaf(a2.y, m2, ay);                        \
        az = fmaf(b2.x, m2, az); aw = fmaf(b2.y, m2, aw);                        \
        ax = fmaf(a3.x, m3, ax); ay = fmaf(a3.y, m3, ay);                        \
        az = fmaf(b3.x, m3, az); aw = fmaf(b3.y, m3, aw);                        \
    }                                                                            \
    for (; e < end; e++) {                                                       \
        uint2 e0 = g_ee[e];                                                      \
        float m0 = __uint_as_float(e0.y);                                        \
        uint2 u0 = ((const uint2*)(H + (size_t)e0.x * HID))[lane];               \
        float2 a0 = h2f(u0.x), b0 = h2f(u0.y);                                   \
        ax = fmaf(a0.x, m0, ax); ay = fmaf(a0.y, m0, ay);                        \
        az = fmaf(b0.x, m0, az); aw = fmaf(b0.y, m0, aw);                        \
    }

__global__ __launch_bounds__(256) void k_prop_csr_split(
    const unsigned short* __restrict__ H,
    const float* __restrict__ b)
{
    int warp = (blockIdx.x * blockDim.x + threadIdx.x) >> 5;
    if (warp >= NN) return;
    int lane = threadIdx.x & 31;

    float di = g_dinv[warp];
    float s = di * di;
    float4 bb = ((const float4*)b)[lane];
    uint2 uv = ((const uint2*)(H + (size_t)warp * HID))[lane];
    float2 v0 = h2f(uv.x), v1 = h2f(uv.y);
    float ax = fmaf(v0.x, s, bb.x);
    float ay = fmaf(v0.y, s, bb.y);
    float az = fmaf(v1.x, s, bb.z);
    float aw = fmaf(v1.y, s, bb.w);

    PROP_BODY_H16()

    ax = fmaxf(ax, 0.f); ay = fmaxf(ay, 0.f);
    az = fmaxf(az, 0.f); aw = fmaxf(aw, 0.f);
    uint32_t w0 = pack_h2(ax, ay);
    uint32_t w1 = pack_h2(az, aw);
    size_t o = (size_t)warp * HID + lane * 4;
    *(uint2*)(g_hb + o) = make_uint2(w0, w1);
}

__global__ __launch_bounds__(256) void k_prop_csr_out(
    const unsigned short* __restrict__ H,
    const float* __restrict__ bmu,
    const float* __restrict__ blv,
    float* __restrict__ out)
{
    int warp = (blockIdx.x * blockDim.x + threadIdx.x) >> 5;
    if (warp >= NN) return;
    int lane = threadIdx.x & 31;

    float di = g_dinv[warp];
    float s = di * di;
    float4 bb;
    float* dstp;
    if (lane < 16) {
        bb = ((const float4*)bmu)[lane];
        dstp = out + (size_t)warp * 64 + lane * 4;
    } else {
        bb = ((const float4*)blv)[lane - 16];
        dstp = out + (size_t)NN * 64 + (size_t)warp * 64 + (lane - 16) * 4;
    }
    uint2 uv = ((const uint2*)(H + (size_t)warp * HID))[lane];
    float2 v0 = h2f(uv.x), v1 = h2f(uv.y);
    float ax = fmaf(v0.x, s, bb.x);
    float ay = fmaf(v0.y, s, bb.y);
    float az = fmaf(v1.x, s, bb.z);
    float aw = fmaf(v1.y, s, bb.w);

    PROP_BODY_H16()

    *(float4*)dstp = make_float4(ax, ay, az, aw);
}

// ---------------------------------------------------------------------------
extern "C" void kernel_launch(void* const* d_in, const int* in_sizes, int n_in,
                              void* d_out, int out_size)
{
    const float* x   = (const float*)d_in[0];
    const int*   ei  = (const int*)d_in[1];
    const float* W1  = (const float*)d_in[2];
    const float* b1  = (const float*)d_in[3];
    const float* Wmu = (const float*)d_in[4];
    const float* bmu = (const float*)d_in[5];
    const float* Wlv = (const float*)d_in[6];
    const float* blv = (const float*)d_in[7];
    float* out = (float*)d_out;

    const int* src = ei;
    const int* dst = ei + NE;

    unsigned short *ha, *hb, *w1, *w2;
    cudaGetSymbolAddress((void**)&ha, g_ha);
    cudaGetSymbolAddress((void**)&hb, g_hb);
    cudaGetSymbolAddress((void**)&w1, g_w1);
    cudaGetSymbolAddress((void**)&w2, g_w2);

    cudaFuncSetAttribute(tgemm_f32a, cudaFuncAttributeMaxDynamicSharedMemorySize, SMEM_GEMM);
    cudaFuncSetAttribute(tgemm_h16, cudaFuncAttributeMaxDynamicSharedMemorySize, SMEM_GEMM);

    const int TB = 256;

    // Side stream + fork/join events (host-side only; created per call)
    cudaStream_t s2;
    cudaStreamCreateWithFlags(&s2, cudaStreamNonBlocking);
    cudaEvent_t ev_fork, ev_join;
    cudaEventCreateWithFlags(&ev_fork, cudaEventDisableTiming);
    cudaEventCreateWithFlags(&ev_join, cudaEventDisableTiming);

    // --- main stream: W1 conversion (GEMM1 dependency) ---
    k_convw1<<<128, TB>>>(W1);

    // --- fork: CSR build on s2, concurrent with GEMM1 on main ---
    cudaEventRecord(ev_fork, 0);
    cudaStreamWaitEvent(s2, ev_fork, 0);

    k_count_init<<<2564, TB, 0, s2>>>(dst, Wmu, Wlv);
    k_alloc<<<NB, 1024, 0, s2>>>();
    k_scatter<<<(NE + TB - 1) / TB, TB, 0, s2>>>(src, dst);
    cudaEventRecord(ev_join, s2);

    // --- main stream: Layer 1 GEMM -> fp16 g_ha ---
    tgemm_f32a<<<(NN + 127) / 128, 256, SMEM_GEMM>>>(x, w1, ha, NN);

    // --- join: prop1 needs both GEMM1 and CSR ---
    cudaStreamWaitEvent(0, ev_join, 0);

    // --- Propagate + ReLU + fp16 pack: g_ha -> g_hb ---
    k_prop_csr_split<<<(NN * 32 + TB - 1) / TB, TB>>>(ha, b1);

    // --- Layer 2: g_hb @ [W_mu | W_logvar] -> fp16 g_ha ---
    tgemm_h16<<<(NN + 127) / 128, 256, SMEM_GEMM>>>(hb, w2, ha, NN);

    // --- Propagate to split fp32 output: g_ha -> out ---
    k_prop_csr_out<<<(NN * 32 + TB - 1) / TB, TB>>>(ha, bmu, blv, out);
}